// round 5
// baseline (speedup 1.0000x reference)
#include <cuda_runtime.h>
#include <cuda_fp16.h>
#include <stdint.h>

// ---------------------------------------------------------------------------
// 2-layer GCN, single persistent kernel. Round 5: wavefront diet.
// fp16 xw1 staging (half gather traffic), 5 blocks/SM, 8-edge batched SpMM.
// ---------------------------------------------------------------------------

#define N_MAXC  100000
#define E_MAXC  1700000
#define FIN1    128
#define HID     64
#define CLS     32
#define NB      640
#define BS      256
#define NT      (NB * BS)

typedef unsigned long long u64;
typedef unsigned int u32;

// ---- device scratch ----
__device__ u64   g_degcnt[N_MAXC];            // (count<<42) | fixed24(sum ew)
__device__ int   g_cnt2[N_MAXC];              // per-dst fill counter
__device__ int   g_rowptr[N_MAXC + 1];
__device__ float g_dinv[N_MAXC];
__device__ int   g_bsums[NB];
__device__ u64   g_csr[E_MAXC];               // (f32bits(norm)<<32) | src
__device__ u32   g_xw1h[(size_t)N_MAXC * 32]; // xw1 as half2 (64 cols), 12.8MB
__device__ float g_xw2[(size_t)N_MAXC * CLS];
__device__ int   g_count;
__device__ int   g_gen;

// ---- packed f32x2 helpers ----
__device__ __forceinline__ u64 ffma2(u64 a, u64 b, u64 c) {
    u64 d;
    asm("fma.rn.f32x2 %0, %1, %2, %3;" : "=l"(d) : "l"(a), "l"(b), "l"(c));
    return d;
}
__device__ __forceinline__ u64 pack2(float x) {
    u64 d;
    asm("mov.b64 %0, {%1, %1};" : "=l"(d) : "r"(__float_as_uint(x)));
    return d;
}
__device__ __forceinline__ float2 unpk(u64 v) {
    float2 f;
    asm("mov.b64 {%0, %1}, %2;" : "=f"(f.x), "=f"(f.y) : "l"(v));
    return f;
}
__device__ __forceinline__ float2 h2f(u32 v) {
    __half2 h = *(__half2*)&v;
    return __half22float2(h);
}

// ---- grid barrier ----
__device__ __forceinline__ void gbar(int expect) {
    __syncthreads();
    if (threadIdx.x == 0) {
        __threadfence();
        int t = atomicAdd(&g_count, 1);
        if (t == NB - 1) {
            g_count = 0;
            __threadfence();
            *(volatile int*)&g_gen = expect;
        } else {
            while (*(volatile int*)&g_gen - expect < 0) {}
            __threadfence();
        }
    }
    __syncthreads();
}

__global__ void __launch_bounds__(BS, 5) mega(
    const float* __restrict__ x, const void* __restrict__ ei,
    const float* __restrict__ ew, const float* __restrict__ W1,
    const float* __restrict__ b1, const float* __restrict__ W2,
    const float* __restrict__ b2, float* __restrict__ out,
    int N, int E)
{
    __shared__ __align__(16) float s_f[FIN1 * HID];   // 32KB: W1, later W2
    __shared__ int    s_scan[BS];
    __shared__ u64    s_ebuf[8][32];
    __shared__ float2 s_hrow2[8][32];
    __shared__ int    s_is64;

    const int tid = threadIdx.x;
    const int b   = blockIdx.x;
    const int gtid = b * BS + tid;

    int ebase = 0;
    if (tid == 0) ebase = *(volatile int*)&g_gen;

    // ---------------- phase A: zero counters + i32/i64 detection ------------
    for (int i = gtid; i < N; i += NT) { g_degcnt[i] = 0ull; g_cnt2[i] = 0; }
    if (tid < 32) {
        const u32* u = (const u32*)ei;
        int cnt = E < 64 ? E : 64;
        bool nz = false;
        for (int j = tid; j < cnt; j += 32) nz |= (u[2 * j + 1] != 0u);
        u32 bl = __ballot_sync(0xffffffffu, nz);
        if (tid == 0) s_is64 = (bl == 0u) ? 1 : 0;
    }
    gbar(ebase + 1);
    const int is64 = s_is64;

    // ---------------- phase B: edge degree atomics + GEMM1 (half2 out) ------
    for (int i = tid; i < FIN1 * HID; i += BS) s_f[i] = W1[i];
    for (int e = gtid; e < E; e += NT) {
        int d = is64 ? (int)((const long long*)ei)[(size_t)E + e]
                     : ((const int*)ei)[(size_t)E + e];
        u64 add = (1ull << 42) | (u64)(u32)__float2uint_rn(ew[e] * 16777216.0f);
        atomicAdd(&g_degcnt[d], add);
    }
    __syncthreads();
    for (int row = gtid; row < N; row += NT) {
        const float4* x4 = (const float4*)(x + (size_t)row * FIN1);
#pragma unroll 1
        for (int jt = 0; jt < 4; jt++) {            // four 16-col tiles
            u64 acc[8];
#pragma unroll
            for (int j = 0; j < 8; j++) acc[j] = 0ull;
#pragma unroll 2
            for (int k4 = 0; k4 < FIN1 / 4; k4++) {
                float4 xv = x4[k4];
                float xs[4] = {xv.x, xv.y, xv.z, xv.w};
#pragma unroll
                for (int kk = 0; kk < 4; kk++) {
                    u64 xp = pack2(xs[kk]);
                    const ulonglong2* wr =
                        (const ulonglong2*)&s_f[(k4 * 4 + kk) * HID + jt * 16];
#pragma unroll
                    for (int j4 = 0; j4 < 4; j4++) {
                        ulonglong2 wv = wr[j4];
                        acc[2 * j4]     = ffma2(xp, wv.x, acc[2 * j4]);
                        acc[2 * j4 + 1] = ffma2(xp, wv.y, acc[2 * j4 + 1]);
                    }
                }
            }
            // convert 16 floats -> 8 half2 -> 2x 16B stores
            u32 h[8];
#pragma unroll
            for (int j = 0; j < 8; j++) {
                float2 f = unpk(acc[j]);
                __half2 hh = __floats2half2_rn(f.x, f.y);
                h[j] = *(u32*)&hh;
            }
            uint4* dst = (uint4*)(g_xw1h + (size_t)row * 32 + jt * 8);
            dst[0] = make_uint4(h[0], h[1], h[2], h[3]);
            dst[1] = make_uint4(h[4], h[5], h[6], h[7]);
        }
    }
    gbar(ebase + 2);

    // ---------------- phase C: dinv + per-block count scan ------------------
    const int CH = (N + NB - 1) / NB;
    const int rbase = b * CH;
    const int rend = (rbase + CH < N) ? (rbase + CH) : N;
    const int r0 = rbase + tid;
    int c0 = 0;
    if (r0 < rend) {
        u64 pc = g_degcnt[r0];
        c0 = (int)(pc >> 42);
        g_dinv[r0] = rsqrtf(1.0f + (float)(pc & ((1ull << 42) - 1)) * (1.0f / 16777216.0f));
    }
    s_scan[tid] = c0;
    __syncthreads();
    for (int off = 1; off < BS; off <<= 1) {
        int a = (tid >= off) ? s_scan[tid - off] : 0;
        __syncthreads();
        s_scan[tid] += a;
        __syncthreads();
    }
    int ex0 = s_scan[tid] - c0;
    if (r0 < rend) g_rowptr[r0] = ex0;
    if (tid == BS - 1) g_bsums[b] = s_scan[BS - 1];
    gbar(ebase + 3);

    // ---------------- phase DE: block offsets + finalize rowptr -------------
    {
        int v = 0;
        for (int j = tid; j < b; j += BS) v += g_bsums[j];
        __syncthreads();
        s_scan[tid] = v;
        __syncthreads();
        for (int off = BS / 2; off > 0; off >>= 1) {
            if (tid < off) s_scan[tid] += s_scan[tid + off];
            __syncthreads();
        }
        int off_b = s_scan[0];
        if (r0 < rend) g_rowptr[r0] += off_b;
        if (gtid == 0) g_rowptr[N] = E;
    }
    gbar(ebase + 4);

    // ---------------- phase F: fill CSR -------------------------------------
    for (int e = gtid; e < E; e += NT) {
        int s, d;
        if (is64) {
            const long long* p = (const long long*)ei;
            s = (int)p[e]; d = (int)p[(size_t)E + e];
        } else {
            const int* p = (const int*)ei;
            s = p[e]; d = p[(size_t)E + e];
        }
        float norm = g_dinv[s] * ew[e] * g_dinv[d];
        int slot = g_rowptr[d] + atomicAdd(&g_cnt2[d], 1);
        g_csr[slot] = ((u64)__float_as_uint(norm) << 32) | (u32)s;
    }
    gbar(ebase + 5);

    // ---------------- phase G: SpMM1 (half2 gather) + fused h@W2 ------------
    for (int i = tid; i < HID * CLS; i += BS) s_f[i] = W2[i];
    __syncthreads();
    const int wid = tid >> 5, lane = tid & 31;
    for (int row = b * 8 + wid; row < N; row += NB * 8) {
        float dn = g_dinv[row];
        float sl = dn * dn;
        float2 self = h2f(g_xw1h[(size_t)row * 32 + lane]);
        float aX = sl * self.x, aY = sl * self.y;     // accum pair A
        float bX = 0.f, bY = 0.f;                     // accum pair B
        int p = g_rowptr[row], pe = g_rowptr[row + 1];
        u64* buf = s_ebuf[wid];
        while (p < pe) {
            int m = pe - p; if (m > 32) m = 32;
            if (lane < m) buf[lane] = g_csr[p + lane];
            __syncwarp();
            int t = 0;
            for (; t + 8 <= m; t += 8) {
                u64 q[8];
#pragma unroll
                for (int i = 0; i < 8; i++) q[i] = buf[t + i];
                u32 v[8];
#pragma unroll
                for (int i = 0; i < 8; i++)
                    v[i] = g_xw1h[(size_t)(u32)q[i] * 32 + lane];
#pragma unroll
                for (int i = 0; i < 8; i += 2) {
                    float w0 = __uint_as_float((u32)(q[i] >> 32));
                    float w1 = __uint_as_float((u32)(q[i + 1] >> 32));
                    float2 f0 = h2f(v[i]);
                    float2 f1 = h2f(v[i + 1]);
                    aX = fmaf(w0, f0.x, aX); aY = fmaf(w0, f0.y, aY);
                    bX = fmaf(w1, f1.x, bX); bY = fmaf(w1, f1.y, bY);
                }
            }
            for (; t < m; t++) {
                u64 q0 = buf[t];
                float w0 = __uint_as_float((u32)(q0 >> 32));
                float2 f0 = h2f(g_xw1h[(size_t)(u32)q0 * 32 + lane]);
                aX = fmaf(w0, f0.x, aX); aY = fmaf(w0, f0.y, aY);
            }
            __syncwarp();
            p += 32;
        }
        float2 bb = ((const float2*)b1)[lane];
        float hx = fmaxf(aX + bX + bb.x, 0.0f);
        float hy = fmaxf(aY + bY + bb.y, 0.0f);
        s_hrow2[wid][lane] = make_float2(hx, hy);
        __syncwarp();
        float acc = 0.0f;
        const float2* hr = s_hrow2[wid];
#pragma unroll
        for (int k2 = 0; k2 < 32; k2++) {
            float2 hv = hr[k2];
            acc = fmaf(hv.x, s_f[(2 * k2) * CLS + lane], acc);
            acc = fmaf(hv.y, s_f[(2 * k2 + 1) * CLS + lane], acc);
        }
        g_xw2[(size_t)row * CLS + lane] = acc;
        __syncwarp();
    }
    gbar(ebase + 6);

    // ---------------- phase H: SpMM2 (F=32, fp32) -> out --------------------
    for (int row = b * 8 + wid; row < N; row += NB * 8) {
        float dn = g_dinv[row];
        float sl = dn * dn;
        float aA = sl * g_xw2[(size_t)row * CLS + lane];
        float aB = 0.f;
        int p = g_rowptr[row], pe = g_rowptr[row + 1];
        u64* buf = s_ebuf[wid];
        while (p < pe) {
            int m = pe - p; if (m > 32) m = 32;
            if (lane < m) buf[lane] = g_csr[p + lane];
            __syncwarp();
            int t = 0;
            for (; t + 8 <= m; t += 8) {
                u64 q[8];
#pragma unroll
                for (int i = 0; i < 8; i++) q[i] = buf[t + i];
                float v[8];
#pragma unroll
                for (int i = 0; i < 8; i++)
                    v[i] = g_xw2[(size_t)(u32)q[i] * CLS + lane];
#pragma unroll
                for (int i = 0; i < 8; i += 2) {
                    aA = fmaf(__uint_as_float((u32)(q[i] >> 32)), v[i], aA);
                    aB = fmaf(__uint_as_float((u32)(q[i + 1] >> 32)), v[i + 1], aB);
                }
            }
            for (; t < m; t++) {
                u64 q0 = buf[t];
                aA = fmaf(__uint_as_float((u32)(q0 >> 32)),
                          g_xw2[(size_t)(u32)q0 * CLS + lane], aA);
            }
            __syncwarp();
            p += 32;
        }
        out[(size_t)row * CLS + lane] = aA + aB + b2[lane];
    }
}

// ---------------------------------------------------------------------------
extern "C" void kernel_launch(void* const* d_in, const int* in_sizes, int n_in,
                              void* d_out, int out_size) {
    const float* x  = (const float*)d_in[0];
    const void*  ei = d_in[1];
    const float* ew = (const float*)d_in[2];
    const float* W1 = (const float*)d_in[3];
    const float* b1 = (const float*)d_in[4];
    const float* W2 = (const float*)d_in[5];
    const float* b2 = (const float*)d_in[6];
    float* out = (float*)d_out;

    int E = in_sizes[2];
    int N = in_sizes[0] / FIN1;
    if (N > N_MAXC) N = N_MAXC;
    if (E > E_MAXC) E = E_MAXC;

    mega<<<NB, BS>>>(x, ei, ew, W1, b1, W2, b2, out, N, E);
}

// round 6
// speedup vs baseline: 1.1743x; 1.1743x over previous
#include <cuda_runtime.h>
#include <stdint.h>

// ---------------------------------------------------------------------------
// 2-layer GCN, single persistent kernel. Round 6: instruction diet in SpMM.
// 16-lane edge-slots (2 edges/warp-step), f32x2 FMA, permuted xw1 layout,
// dinv[dst] factored out of CSR weights. GEMM = proven round-4 shape.
// ---------------------------------------------------------------------------

#define N_MAXC  100000
#define E_MAXC  1700000
#define FIN1    128
#define HID     64
#define CLS     32
#define NB      512
#define BS      256
#define NT      (NB * BS)

typedef unsigned long long u64;
typedef unsigned int u32;

// ---- device scratch ----
__device__ u64        g_degcnt[N_MAXC];        // (count<<42) | fixed24(sum ew)
__device__ int        g_cnt2[N_MAXC];
__device__ int        g_rowptr[N_MAXC + 1];
__device__ float      g_dinv[N_MAXC];
__device__ int        g_bsums[NB];
__device__ u64        g_csr[E_MAXC];           // (f32bits(dinv[s]*ew)<<32)|src
__device__ ulonglong2 g_xw1v[(size_t)N_MAXC * 16];  // permuted xw1, 25.6MB
__device__ ulonglong2 g_xw2v[(size_t)N_MAXC * 8];   // xw2 natural, 12.8MB
__device__ int        g_count;
__device__ int        g_gen;

// ---- packed f32x2 helpers ----
__device__ __forceinline__ u64 ffma2(u64 a, u64 b, u64 c) {
    u64 d;
    asm("fma.rn.f32x2 %0, %1, %2, %3;" : "=l"(d) : "l"(a), "l"(b), "l"(c));
    return d;
}
__device__ __forceinline__ u64 dup2(u32 w) {
    u64 d;
    asm("mov.b64 %0, {%1, %1};" : "=l"(d) : "r"(w));
    return d;
}
__device__ __forceinline__ u64 pack2f(float x, float y) {
    u64 d;
    asm("mov.b64 %0, {%1, %2};" : "=l"(d) : "r"(__float_as_uint(x)), "r"(__float_as_uint(y)));
    return d;
}
__device__ __forceinline__ float2 unpk(u64 v) {
    float2 f;
    asm("mov.b64 {%0, %1}, %2;" : "=f"(f.x), "=f"(f.y) : "l"(v));
    return f;
}

// ---- grid barrier ----
__device__ __forceinline__ void gbar(int expect) {
    __syncthreads();
    if (threadIdx.x == 0) {
        __threadfence();
        int t = atomicAdd(&g_count, 1);
        if (t == NB - 1) {
            g_count = 0;
            __threadfence();
            *(volatile int*)&g_gen = expect;
        } else {
            while (*(volatile int*)&g_gen - expect < 0) {}
            __threadfence();
        }
    }
    __syncthreads();
}

__global__ void __launch_bounds__(BS, 4) mega(
    const float* __restrict__ x, const void* __restrict__ ei,
    const float* __restrict__ ew, const float* __restrict__ W1,
    const float* __restrict__ b1, const float* __restrict__ W2,
    const float* __restrict__ b2, float* __restrict__ out,
    int N, int E)
{
    __shared__ __align__(16) float s_f[FIN1 * HID];   // 32KB: W1, later W2
    __shared__ int   s_scan[BS];
    __shared__ u64   s_ebuf[8][32];
    __shared__ __align__(16) float s_hrow[8][HID];
    __shared__ int   s_is64;

    const int tid = threadIdx.x;
    const int b   = blockIdx.x;
    const int gtid = b * BS + tid;

    int ebase = 0;
    if (tid == 0) ebase = *(volatile int*)&g_gen;

    // ---------------- phase A: zero counters + i32/i64 detection ------------
    for (int i = gtid; i < N; i += NT) { g_degcnt[i] = 0ull; g_cnt2[i] = 0; }
    if (tid < 32) {
        const u32* u = (const u32*)ei;
        int cnt = E < 64 ? E : 64;
        bool nz = false;
        for (int j = tid; j < cnt; j += 32) nz |= (u[2 * j + 1] != 0u);
        u32 bl = __ballot_sync(0xffffffffu, nz);
        if (tid == 0) s_is64 = (bl == 0u) ? 1 : 0;
    }
    gbar(ebase + 1);
    const int is64 = s_is64;

    // ---------------- phase B: edge degree atomics + GEMM1 ------------------
    for (int i = tid; i < FIN1 * HID; i += BS) s_f[i] = W1[i];
    for (int e = gtid; e < E; e += NT) {
        int d = is64 ? (int)((const long long*)ei)[(size_t)E + e]
                     : ((const int*)ei)[(size_t)E + e];
        u64 add = (1ull << 42) | (u64)(u32)__float2uint_rn(ew[e] * 16777216.0f);
        atomicAdd(&g_degcnt[d], add);
    }
    __syncthreads();
    for (int row = gtid; row < N; row += NT) {
        const float4* x4 = (const float4*)(x + (size_t)row * FIN1);
        u64* yo = (u64*)(g_xw1v + (size_t)row * 16);
#pragma unroll 1
        for (int jt = 0; jt < 2; jt++) {          // two 32-col passes
            u64 acc[16];
#pragma unroll
            for (int j = 0; j < 16; j++) acc[j] = 0ull;
#pragma unroll 2
            for (int k4 = 0; k4 < FIN1 / 4; k4++) {
                float4 xv = x4[k4];
                float xs[4] = {xv.x, xv.y, xv.z, xv.w};
#pragma unroll
                for (int kk = 0; kk < 4; kk++) {
                    u64 xp = dup2(__float_as_uint(xs[kk]));
                    const ulonglong2* wr =
                        (const ulonglong2*)&s_f[(k4 * 4 + kk) * HID + jt * 32];
#pragma unroll
                    for (int j4 = 0; j4 < 8; j4++) {
                        ulonglong2 wv = wr[j4];
                        acc[2 * j4]     = ffma2(xp, wv.x, acc[2 * j4]);
                        acc[2 * j4 + 1] = ffma2(xp, wv.y, acc[2 * j4 + 1]);
                    }
                }
            }
            // permuted store: logical col (jt*32 + 2j, +1) -> u64 slot 2j + jt
#pragma unroll
            for (int j = 0; j < 16; j++) yo[2 * j + jt] = acc[j];
        }
    }
    gbar(ebase + 2);

    // ---------------- phase C: dinv + per-block count scan ------------------
    const int CH = (N + NB - 1) / NB;
    const int rbase = b * CH;
    const int rend = (rbase + CH < N) ? (rbase + CH) : N;
    const int r0 = rbase + tid;
    int c0 = 0;
    if (r0 < rend) {
        u64 pc = g_degcnt[r0];
        c0 = (int)(pc >> 42);
        g_dinv[r0] = rsqrtf(1.0f + (float)(pc & ((1ull << 42) - 1)) * (1.0f / 16777216.0f));
    }
    s_scan[tid] = c0;
    __syncthreads();
    for (int off = 1; off < BS; off <<= 1) {
        int a = (tid >= off) ? s_scan[tid - off] : 0;
        __syncthreads();
        s_scan[tid] += a;
        __syncthreads();
    }
    int ex0 = s_scan[tid] - c0;
    if (r0 < rend) g_rowptr[r0] = ex0;
    if (tid == BS - 1) g_bsums[b] = s_scan[BS - 1];
    gbar(ebase + 3);

    // ---------------- phase DE: block offsets + finalize rowptr -------------
    {
        int v = 0;
        for (int j = tid; j < b; j += BS) v += g_bsums[j];
        __syncthreads();
        s_scan[tid] = v;
        __syncthreads();
        for (int off = BS / 2; off > 0; off >>= 1) {
            if (tid < off) s_scan[tid] += s_scan[tid + off];
            __syncthreads();
        }
        int off_b = s_scan[0];
        if (r0 < rend) g_rowptr[r0] += off_b;
        if (gtid == 0) g_rowptr[N] = E;
    }
    gbar(ebase + 4);

    // ---------------- phase F: fill CSR (w' = dinv[src]*ew) -----------------
    for (int e = gtid; e < E; e += NT) {
        int s, d;
        if (is64) {
            const long long* p = (const long long*)ei;
            s = (int)p[e]; d = (int)p[(size_t)E + e];
        } else {
            const int* p = (const int*)ei;
            s = p[e]; d = p[(size_t)E + e];
        }
        float wp = g_dinv[s] * ew[e];
        int slot = g_rowptr[d] + atomicAdd(&g_cnt2[d], 1);
        g_csr[slot] = ((u64)__float_as_uint(wp) << 32) | (u32)s;
    }
    gbar(ebase + 5);

    // ---------------- phase G: SpMM1 (2 edge-slots, f32x2) + fused h@W2 -----
    for (int i = tid; i < HID * CLS; i += BS) s_f[i] = W2[i];
    __syncthreads();
    const int wid = tid >> 5, lane = tid & 31;
    const int slot = lane >> 4, cc = lane & 15;
    // per-lane bias (logical cols 2cc, 2cc+1, 32+2cc, 33+2cc)
    float b1a = b1[2 * cc], b1b = b1[2 * cc + 1];
    float b1c = b1[32 + 2 * cc], b1d = b1[33 + 2 * cc];
    u64* buf = s_ebuf[wid];
    for (int row = b * 8 + wid; row < N; row += NB * 8) {
        float dn = g_dinv[row];
        u64 acc01 = 0ull, acc23 = 0ull;
        if (slot == 0) {
            float4 sv = ((const float4*)(g_xw1v + (size_t)row * 16))[cc];
            acc01 = pack2f(dn * sv.x, dn * sv.y);
            acc23 = pack2f(dn * sv.z, dn * sv.w);
        }
        int p = g_rowptr[row], pe = g_rowptr[row + 1];
        while (p < pe) {
            int m = pe - p; if (m > 32) m = 32;
            buf[lane] = (lane < m) ? g_csr[p + lane] : 0ull;
            __syncwarp();
            int pairs = (m + 1) >> 1;
            int t = 0;
            for (; t + 4 <= pairs; t += 4) {
                u64 q0 = buf[2 * t + slot],     q1 = buf[2 * t + 2 + slot];
                u64 q2 = buf[2 * t + 4 + slot], q3 = buf[2 * t + 6 + slot];
                ulonglong2 v0 = g_xw1v[(size_t)(u32)q0 * 16 + cc];
                ulonglong2 v1 = g_xw1v[(size_t)(u32)q1 * 16 + cc];
                ulonglong2 v2 = g_xw1v[(size_t)(u32)q2 * 16 + cc];
                ulonglong2 v3 = g_xw1v[(size_t)(u32)q3 * 16 + cc];
                u64 w0 = dup2((u32)(q0 >> 32)), w1 = dup2((u32)(q1 >> 32));
                u64 w2 = dup2((u32)(q2 >> 32)), w3 = dup2((u32)(q3 >> 32));
                acc01 = ffma2(w0, v0.x, acc01); acc23 = ffma2(w0, v0.y, acc23);
                acc01 = ffma2(w1, v1.x, acc01); acc23 = ffma2(w1, v1.y, acc23);
                acc01 = ffma2(w2, v2.x, acc01); acc23 = ffma2(w2, v2.y, acc23);
                acc01 = ffma2(w3, v3.x, acc01); acc23 = ffma2(w3, v3.y, acc23);
            }
            for (; t < pairs; t++) {
                u64 q0 = buf[2 * t + slot];
                ulonglong2 v0 = g_xw1v[(size_t)(u32)q0 * 16 + cc];
                u64 w0 = dup2((u32)(q0 >> 32));
                acc01 = ffma2(w0, v0.x, acc01); acc23 = ffma2(w0, v0.y, acc23);
            }
            __syncwarp();
            p += 32;
        }
        // combine slots + apply dinv[dst] + bias + relu
        float2 a01 = unpk(acc01), a23 = unpk(acc23);
        a01.x += __shfl_xor_sync(0xffffffffu, a01.x, 16);
        a01.y += __shfl_xor_sync(0xffffffffu, a01.y, 16);
        a23.x += __shfl_xor_sync(0xffffffffu, a23.x, 16);
        a23.y += __shfl_xor_sync(0xffffffffu, a23.y, 16);
        float hx = fmaxf(dn * a01.x + b1a, 0.0f);
        float hy = fmaxf(dn * a01.y + b1b, 0.0f);
        float hz = fmaxf(dn * a23.x + b1c, 0.0f);
        float hw = fmaxf(dn * a23.y + b1d, 0.0f);
        if (slot == 0)
            ((float4*)s_hrow[wid])[cc] = make_float4(hx, hy, hz, hw);
        __syncwarp();
        // projection: xw2[row, lane] = sum_k h[k]*W2[k,lane] (permuted h)
        float acc = 0.0f;
        const float4* hr = (const float4*)s_hrow[wid];
#pragma unroll
        for (int c2 = 0; c2 < 16; c2++) {
            float4 hv = hr[c2];
            acc = fmaf(hv.x, s_f[(2 * c2) * CLS + lane], acc);
            acc = fmaf(hv.y, s_f[(2 * c2 + 1) * CLS + lane], acc);
            acc = fmaf(hv.z, s_f[(32 + 2 * c2) * CLS + lane], acc);
            acc = fmaf(hv.w, s_f[(33 + 2 * c2) * CLS + lane], acc);
        }
        ((float*)(g_xw2v + (size_t)row * 8))[lane] = acc;
        __syncwarp();
    }
    gbar(ebase + 6);

    // ---------------- phase H: SpMM2 (2 edge-slots, f32x2) -> out -----------
    {
        float2 b2v = ((const float2*)b2)[cc];
        for (int row = b * 8 + wid; row < N; row += NB * 8) {
            float dn = g_dinv[row];
            u64 acc = 0ull;
            if (slot == 0) {
                float2 sv = ((const float2*)(g_xw2v + (size_t)row * 8))[cc];
                acc = pack2f(dn * sv.x, dn * sv.y);
            }
            int p = g_rowptr[row], pe = g_rowptr[row + 1];
            const u64* X2 = (const u64*)g_xw2v;
            while (p < pe) {
                int m = pe - p; if (m > 32) m = 32;
                buf[lane] = (lane < m) ? g_csr[p + lane] : 0ull;
                __syncwarp();
                int pairs = (m + 1) >> 1;
                int t = 0;
                for (; t + 4 <= pairs; t += 4) {
                    u64 q0 = buf[2 * t + slot],     q1 = buf[2 * t + 2 + slot];
                    u64 q2 = buf[2 * t + 4 + slot], q3 = buf[2 * t + 6 + slot];
                    u64 v0 = X2[(size_t)(u32)q0 * 16 + cc];
                    u64 v1 = X2[(size_t)(u32)q1 * 16 + cc];
                    u64 v2 = X2[(size_t)(u32)q2 * 16 + cc];
                    u64 v3 = X2[(size_t)(u32)q3 * 16 + cc];
                    acc = ffma2(dup2((u32)(q0 >> 32)), v0, acc);
                    acc = ffma2(dup2((u32)(q1 >> 32)), v1, acc);
                    acc = ffma2(dup2((u32)(q2 >> 32)), v2, acc);
                    acc = ffma2(dup2((u32)(q3 >> 32)), v3, acc);
                }
                for (; t < pairs; t++) {
                    u64 q0 = buf[2 * t + slot];
                    acc = ffma2(dup2((u32)(q0 >> 32)),
                                X2[(size_t)(u32)q0 * 16 + cc], acc);
                }
                __syncwarp();
                p += 32;
            }
            float2 a = unpk(acc);
            a.x += __shfl_xor_sync(0xffffffffu, a.x, 16);
            a.y += __shfl_xor_sync(0xffffffffu, a.y, 16);
            if (slot == 0)
                ((float2*)(out + (size_t)row * CLS))[cc] =
                    make_float2(dn * a.x + b2v.x, dn * a.y + b2v.y);
        }
    }
}

// ---------------------------------------------------------------------------
extern "C" void kernel_launch(void* const* d_in, const int* in_sizes, int n_in,
                              void* d_out, int out_size) {
    const float* x  = (const float*)d_in[0];
    const void*  ei = d_in[1];
    const float* ew = (const float*)d_in[2];
    const float* W1 = (const float*)d_in[3];
    const float* b1 = (const float*)d_in[4];
    const float* W2 = (const float*)d_in[5];
    const float* b2 = (const float*)d_in[6];
    float* out = (float*)d_out;

    int E = in_sizes[2];
    int N = in_sizes[0] / FIN1;
    if (N > N_MAXC) N = N_MAXC;
    if (E > E_MAXC) E = E_MAXC;

    mega<<<NB, BS>>>(x, ei, ew, W1, b1, W2, b2, out, N, E);
}

// round 7
// speedup vs baseline: 1.4441x; 1.2298x over previous
#include <cuda_runtime.h>
#include <stdint.h>

// ---------------------------------------------------------------------------
// 2-layer GCN, single persistent kernel. Round 7: block-tiled GEMM.
// Coalesced X staging + chunked W streaming + smem-transposed epilogue.
// SpMM phases identical to round 6 (16-lane edge slots, f32x2).
// ---------------------------------------------------------------------------

#define N_MAXC  100000
#define E_MAXC  1700000
#define FIN1    128
#define HID     64
#define CLS     32
#define NB      512
#define BS      256
#define NT      (NB * BS)

typedef unsigned long long u64;
typedef unsigned int u32;

// ---- device scratch ----
__device__ u64        g_degcnt[N_MAXC];        // (count<<42) | fixed24(sum ew)
__device__ int        g_cnt2[N_MAXC];
__device__ int        g_rowptr[N_MAXC + 1];
__device__ float      g_dinv[N_MAXC];
__device__ int        g_bsums[NB];
__device__ u64        g_csr[E_MAXC];           // (f32bits(dinv[s]*ew)<<32)|src
__device__ ulonglong2 g_xw1v[(size_t)N_MAXC * 16];  // permuted xw1, 25.6MB
__device__ ulonglong2 g_xw2v[(size_t)N_MAXC * 8];   // xw2 natural, 12.8MB
__device__ int        g_count;
__device__ int        g_gen;

// ---- packed f32x2 helpers ----
__device__ __forceinline__ u64 ffma2(u64 a, u64 b, u64 c) {
    u64 d;
    asm("fma.rn.f32x2 %0, %1, %2, %3;" : "=l"(d) : "l"(a), "l"(b), "l"(c));
    return d;
}
__device__ __forceinline__ u64 dup2(u32 w) {
    u64 d;
    asm("mov.b64 %0, {%1, %1};" : "=l"(d) : "r"(w));
    return d;
}
__device__ __forceinline__ u64 pack2f(float x, float y) {
    u64 d;
    asm("mov.b64 %0, {%1, %2};" : "=l"(d) : "r"(__float_as_uint(x)), "r"(__float_as_uint(y)));
    return d;
}
__device__ __forceinline__ float2 unpk(u64 v) {
    float2 f;
    asm("mov.b64 {%0, %1}, %2;" : "=f"(f.x), "=f"(f.y) : "l"(v));
    return f;
}

// ---- grid barrier ----
__device__ __forceinline__ void gbar(int expect) {
    __syncthreads();
    if (threadIdx.x == 0) {
        __threadfence();
        int t = atomicAdd(&g_count, 1);
        if (t == NB - 1) {
            g_count = 0;
            __threadfence();
            *(volatile int*)&g_gen = expect;
        } else {
            while (*(volatile int*)&g_gen - expect < 0) {}
            __threadfence();
        }
    }
    __syncthreads();
}

__global__ void __launch_bounds__(BS, 4) mega(
    const float* __restrict__ x, const void* __restrict__ ei,
    const float* __restrict__ ew, const float* __restrict__ W1,
    const float* __restrict__ b1, const float* __restrict__ W2,
    const float* __restrict__ b2, float* __restrict__ out,
    int N, int E)
{
    // 37.9KB shared arena, aliased per phase
    __shared__ __align__(16) char s_mem[33792 + 4096];
    __shared__ int s_is64;

    float* sX   = (float*)s_mem;                  // GEMM: [64][132] floats
    float* sW   = (float*)(s_mem + 33792);        // GEMM: [16][64] W chunk
    u64*   sEpi = (u64*)s_mem;                    // GEMM epi: [64][33] u64
    int*   s_scan = (int*)s_mem;                  // scans: [256] int
    float* s_f  = (float*)s_mem;                  // SpMM: W2 [64*32] 8KB
    u64 (*s_ebuf)[32] = (u64(*)[32])(s_mem + 8192);        // 8 warps x 32 u64
    float (*s_hrow)[HID] = (float(*)[HID])(s_mem + 8192 + 2048);

    const int tid = threadIdx.x;
    const int b   = blockIdx.x;
    const int gtid = b * BS + tid;
    const int wid = tid >> 5, lane = tid & 31;

    int ebase = 0;
    if (tid == 0) ebase = *(volatile int*)&g_gen;

    // ---------------- phase A: zero counters + i32/i64 detection ------------
    for (int i = gtid; i < N; i += NT) { g_degcnt[i] = 0ull; g_cnt2[i] = 0; }
    if (tid < 32) {
        const u32* u = (const u32*)ei;
        int cnt = E < 64 ? E : 64;
        bool nz = false;
        for (int j = tid; j < cnt; j += 32) nz |= (u[2 * j + 1] != 0u);
        u32 bl = __ballot_sync(0xffffffffu, nz);
        if (tid == 0) s_is64 = (bl == 0u) ? 1 : 0;
    }
    gbar(ebase + 1);
    const int is64 = s_is64;

    // ---------------- phase B: edge degree atomics + tiled GEMM1 ------------
    for (int e = gtid; e < E; e += NT) {
        int d = is64 ? (int)((const long long*)ei)[(size_t)E + e]
                     : ((const int*)ei)[(size_t)E + e];
        u64 add = (1ull << 42) | (u64)(u32)__float2uint_rn(ew[e] * 16777216.0f);
        atomicAdd(&g_degcnt[d], add);
    }
    __syncthreads();
    {
        const int ntiles = (N + 63) / 64;
        const int w8 = wid * 8;                          // this warp's col base
        const int wb = 8 * (wid & 3) + (wid >> 2);       // permuted u64 slot base
        for (int tile = b; tile < ntiles; tile += NB) {
            const int row0 = tile * 64;
            // stage X tile [64][132] coalesced
            for (int i = tid; i < 2048; i += BS) {       // 2048 float4
                int r = i >> 5, k4 = i & 31;
                float4 v = make_float4(0.f, 0.f, 0.f, 0.f);
                if (row0 + r < N)
                    v = ((const float4*)(x + (size_t)(row0 + r) * FIN1))[k4];
                *(float4*)&sX[r * 132 + 4 * k4] = v;
            }
            __syncthreads();

            u64 accA[4], accB[4];                         // rows lane, lane+32
#pragma unroll
            for (int j = 0; j < 4; j++) { accA[j] = 0ull; accB[j] = 0ull; }

            for (int c = 0; c < 8; c++) {                 // 16-k chunks
                {   // stage W chunk [16][64]: 1024 floats, 1 float4/thread
                    int k = tid >> 4, c4 = tid & 15;
                    *(float4*)&sW[k * 64 + 4 * c4] =
                        ((const float4*)(W1 + (size_t)(c * 16 + k) * HID))[c4];
                }
                __syncthreads();
                const float4* xpA = (const float4*)&sX[lane * 132 + c * 16];
                const float4* xpB = (const float4*)&sX[(lane + 32) * 132 + c * 16];
#pragma unroll
                for (int k4 = 0; k4 < 4; k4++) {
                    float4 xa = xpA[k4];
                    float4 xb = xpB[k4];
                    float xsA[4] = {xa.x, xa.y, xa.z, xa.w};
                    float xsB[4] = {xb.x, xb.y, xb.z, xb.w};
#pragma unroll
                    for (int kk = 0; kk < 4; kk++) {
                        int k = k4 * 4 + kk;
                        ulonglong2 wv0 = *(const ulonglong2*)&sW[k * 64 + w8];
                        ulonglong2 wv1 = *(const ulonglong2*)&sW[k * 64 + w8 + 4];
                        u64 xA = dup2(__float_as_uint(xsA[kk]));
                        u64 xB = dup2(__float_as_uint(xsB[kk]));
                        accA[0] = ffma2(xA, wv0.x, accA[0]);
                        accA[1] = ffma2(xA, wv0.y, accA[1]);
                        accA[2] = ffma2(xA, wv1.x, accA[2]);
                        accA[3] = ffma2(xA, wv1.y, accA[3]);
                        accB[0] = ffma2(xB, wv0.x, accB[0]);
                        accB[1] = ffma2(xB, wv0.y, accB[1]);
                        accB[2] = ffma2(xB, wv1.x, accB[2]);
                        accB[3] = ffma2(xB, wv1.y, accB[3]);
                    }
                }
                __syncthreads();                          // before W restage
            }
            // epilogue: transpose through smem, coalesced permuted store
#pragma unroll
            for (int p = 0; p < 4; p++) {
                sEpi[lane * 33 + wb + 2 * p] = accA[p];
                sEpi[(lane + 32) * 33 + wb + 2 * p] = accB[p];
            }
            __syncthreads();
            u64* xw1u = (u64*)g_xw1v;
            for (int i = tid; i < 2048; i += BS) {        // 64 rows x 32 slots
                int r = i >> 5, s = i & 31;
                if (row0 + r < N)
                    xw1u[(size_t)(row0 + r) * 32 + s] = sEpi[r * 33 + s];
            }
            __syncthreads();
        }
    }
    gbar(ebase + 2);

    // ---------------- phase C: dinv + per-block count scan ------------------
    const int CH = (N + NB - 1) / NB;
    const int rbase = b * CH;
    const int rend = (rbase + CH < N) ? (rbase + CH) : N;
    const int r0 = rbase + tid;
    int c0 = 0;
    if (r0 < rend) {
        u64 pc = g_degcnt[r0];
        c0 = (int)(pc >> 42);
        g_dinv[r0] = rsqrtf(1.0f + (float)(pc & ((1ull << 42) - 1)) * (1.0f / 16777216.0f));
    }
    s_scan[tid] = c0;
    __syncthreads();
    for (int off = 1; off < BS; off <<= 1) {
        int a = (tid >= off) ? s_scan[tid - off] : 0;
        __syncthreads();
        s_scan[tid] += a;
        __syncthreads();
    }
    int ex0 = s_scan[tid] - c0;
    if (r0 < rend) g_rowptr[r0] = ex0;
    if (tid == BS - 1) g_bsums[b] = s_scan[BS - 1];
    gbar(ebase + 3);

    // ---------------- phase DE: block offsets + finalize rowptr -------------
    {
        int v = 0;
        for (int j = tid; j < b; j += BS) v += g_bsums[j];
        __syncthreads();
        s_scan[tid] = v;
        __syncthreads();
        for (int off = BS / 2; off > 0; off >>= 1) {
            if (tid < off) s_scan[tid] += s_scan[tid + off];
            __syncthreads();
        }
        int off_b = s_scan[0];
        if (r0 < rend) g_rowptr[r0] += off_b;
        if (gtid == 0) g_rowptr[N] = E;
    }
    gbar(ebase + 4);

    // ---------------- phase F: fill CSR (w' = dinv[src]*ew) -----------------
    for (int e = gtid; e < E; e += NT) {
        int s, d;
        if (is64) {
            const long long* p = (const long long*)ei;
            s = (int)p[e]; d = (int)p[(size_t)E + e];
        } else {
            const int* p = (const int*)ei;
            s = p[e]; d = p[(size_t)E + e];
        }
        float wp = g_dinv[s] * ew[e];
        int slot = g_rowptr[d] + atomicAdd(&g_cnt2[d], 1);
        g_csr[slot] = ((u64)__float_as_uint(wp) << 32) | (u32)s;
    }
    gbar(ebase + 5);

    // ---------------- phase G: SpMM1 (2 edge-slots, f32x2) + fused h@W2 -----
    for (int i = tid; i < HID * CLS; i += BS) s_f[i] = W2[i];
    __syncthreads();
    const int slot = lane >> 4, cc = lane & 15;
    float b1a = b1[2 * cc], b1b = b1[2 * cc + 1];
    float b1c = b1[32 + 2 * cc], b1d = b1[33 + 2 * cc];
    u64* buf = s_ebuf[wid];
    for (int row = b * 8 + wid; row < N; row += NB * 8) {
        float dn = g_dinv[row];
        u64 acc01 = 0ull, acc23 = 0ull;
        if (slot == 0) {
            float4 sv = ((const float4*)(g_xw1v + (size_t)row * 16))[cc];
            acc01 = pack2f(dn * sv.x, dn * sv.y);
            acc23 = pack2f(dn * sv.z, dn * sv.w);
        }
        int p = g_rowptr[row], pe = g_rowptr[row + 1];
        while (p < pe) {
            int m = pe - p; if (m > 32) m = 32;
            buf[lane] = (lane < m) ? g_csr[p + lane] : 0ull;
            __syncwarp();
            int pairs = (m + 1) >> 1;
            int t = 0;
            for (; t + 4 <= pairs; t += 4) {
                u64 q0 = buf[2 * t + slot],     q1 = buf[2 * t + 2 + slot];
                u64 q2 = buf[2 * t + 4 + slot], q3 = buf[2 * t + 6 + slot];
                ulonglong2 v0 = g_xw1v[(size_t)(u32)q0 * 16 + cc];
                ulonglong2 v1 = g_xw1v[(size_t)(u32)q1 * 16 + cc];
                ulonglong2 v2 = g_xw1v[(size_t)(u32)q2 * 16 + cc];
                ulonglong2 v3 = g_xw1v[(size_t)(u32)q3 * 16 + cc];
                u64 w0 = dup2((u32)(q0 >> 32)), w1 = dup2((u32)(q1 >> 32));
                u64 w2 = dup2((u32)(q2 >> 32)), w3 = dup2((u32)(q3 >> 32));
                acc01 = ffma2(w0, v0.x, acc01); acc23 = ffma2(w0, v0.y, acc23);
                acc01 = ffma2(w1, v1.x, acc01); acc23 = ffma2(w1, v1.y, acc23);
                acc01 = ffma2(w2, v2.x, acc01); acc23 = ffma2(w2, v2.y, acc23);
                acc01 = ffma2(w3, v3.x, acc01); acc23 = ffma2(w3, v3.y, acc23);
            }
            for (; t < pairs; t++) {
                u64 q0 = buf[2 * t + slot];
                ulonglong2 v0 = g_xw1v[(size_t)(u32)q0 * 16 + cc];
                u64 w0 = dup2((u32)(q0 >> 32));
                acc01 = ffma2(w0, v0.x, acc01); acc23 = ffma2(w0, v0.y, acc23);
            }
            __syncwarp();
            p += 32;
        }
        float2 a01 = unpk(acc01), a23 = unpk(acc23);
        a01.x += __shfl_xor_sync(0xffffffffu, a01.x, 16);
        a01.y += __shfl_xor_sync(0xffffffffu, a01.y, 16);
        a23.x += __shfl_xor_sync(0xffffffffu, a23.x, 16);
        a23.y += __shfl_xor_sync(0xffffffffu, a23.y, 16);
        float hx = fmaxf(dn * a01.x + b1a, 0.0f);
        float hy = fmaxf(dn * a01.y + b1b, 0.0f);
        float hz = fmaxf(dn * a23.x + b1c, 0.0f);
        float hw = fmaxf(dn * a23.y + b1d, 0.0f);
        if (slot == 0)
            ((float4*)s_hrow[wid])[cc] = make_float4(hx, hy, hz, hw);
        __syncwarp();
        float acc = 0.0f;
        const float4* hr = (const float4*)s_hrow[wid];
#pragma unroll
        for (int c2 = 0; c2 < 16; c2++) {
            float4 hv = hr[c2];
            acc = fmaf(hv.x, s_f[(2 * c2) * CLS + lane], acc);
            acc = fmaf(hv.y, s_f[(2 * c2 + 1) * CLS + lane], acc);
            acc = fmaf(hv.z, s_f[(32 + 2 * c2) * CLS + lane], acc);
            acc = fmaf(hv.w, s_f[(33 + 2 * c2) * CLS + lane], acc);
        }
        ((float*)(g_xw2v + (size_t)row * 8))[lane] = acc;
        __syncwarp();
    }
    gbar(ebase + 6);

    // ---------------- phase H: SpMM2 (2 edge-slots, f32x2) -> out -----------
    {
        float2 b2v = ((const float2*)b2)[cc];
        for (int row = b * 8 + wid; row < N; row += NB * 8) {
            float dn = g_dinv[row];
            u64 acc = 0ull;
            if (slot == 0) {
                float2 sv = ((const float2*)(g_xw2v + (size_t)row * 8))[cc];
                acc = pack2f(dn * sv.x, dn * sv.y);
            }
            int p = g_rowptr[row], pe = g_rowptr[row + 1];
            const u64* X2 = (const u64*)g_xw2v;
            while (p < pe) {
                int m = pe - p; if (m > 32) m = 32;
                buf[lane] = (lane < m) ? g_csr[p + lane] : 0ull;
                __syncwarp();
                int pairs = (m + 1) >> 1;
                int t = 0;
                for (; t + 4 <= pairs; t += 4) {
                    u64 q0 = buf[2 * t + slot],     q1 = buf[2 * t + 2 + slot];
                    u64 q2 = buf[2 * t + 4 + slot], q3 = buf[2 * t + 6 + slot];
                    u64 v0 = X2[(size_t)(u32)q0 * 16 + cc];
                    u64 v1 = X2[(size_t)(u32)q1 * 16 + cc];
                    u64 v2 = X2[(size_t)(u32)q2 * 16 + cc];
                    u64 v3 = X2[(size_t)(u32)q3 * 16 + cc];
                    acc = ffma2(dup2((u32)(q0 >> 32)), v0, acc);
                    acc = ffma2(dup2((u32)(q1 >> 32)), v1, acc);
                    acc = ffma2(dup2((u32)(q2 >> 32)), v2, acc);
                    acc = ffma2(dup2((u32)(q3 >> 32)), v3, acc);
                }
                for (; t < pairs; t++) {
                    u64 q0 = buf[2 * t + slot];
                    acc = ffma2(dup2((u32)(q0 >> 32)),
                                X2[(size_t)(u32)q0 * 16 + cc], acc);
                }
                __syncwarp();
                p += 32;
            }
            float2 a = unpk(acc);
            a.x += __shfl_xor_sync(0xffffffffu, a.x, 16);
            a.y += __shfl_xor_sync(0xffffffffu, a.y, 16);
            if (slot == 0)
                ((float2*)(out + (size_t)row * CLS))[cc] =
                    make_float2(dn * a.x + b2v.x, dn * a.y + b2v.y);
        }
    }
}

// ---------------------------------------------------------------------------
extern "C" void kernel_launch(void* const* d_in, const int* in_sizes, int n_in,
                              void* d_out, int out_size) {
    const float* x  = (const float*)d_in[0];
    const void*  ei = d_in[1];
    const float* ew = (const float*)d_in[2];
    const float* W1 = (const float*)d_in[3];
    const float* b1 = (const float*)d_in[4];
    const float* W2 = (const float*)d_in[5];
    const float* b2 = (const float*)d_in[6];
    float* out = (float*)d_out;

    int E = in_sizes[2];
    int N = in_sizes[0] / FIN1;
    if (N > N_MAXC) N = N_MAXC;
    if (E > E_MAXC) E = E_MAXC;

    mega<<<NB, BS>>>(x, ei, ew, W1, b1, W2, b2, out, N, E);
}

// round 8
// speedup vs baseline: 1.5317x; 1.0607x over previous
#include <cuda_runtime.h>
#include <stdint.h>

// ---------------------------------------------------------------------------
// 2-layer GCN, single persistent kernel. Round 8: dynamic work-stealing.
// GEMM tiles + SpMM 8-row chunks dispensed by atomic tickets; contiguous
// row chunks give sequential CSR access. Core math identical to round 7.
// ---------------------------------------------------------------------------

#define N_MAXC  100000
#define E_MAXC  1700000
#define FIN1    128
#define HID     64
#define CLS     32
#define NB      512
#define BS      256
#define NT      (NB * BS)

typedef unsigned long long u64;
typedef unsigned int u32;

// ---- device scratch ----
__device__ u64        g_degcnt[N_MAXC];        // (count<<42) | fixed24(sum ew)
__device__ int        g_cnt2[N_MAXC];
__device__ int        g_rowptr[N_MAXC + 1];
__device__ float      g_dinv[N_MAXC];
__device__ int        g_bsums[NB];
__device__ u64        g_csr[E_MAXC];           // (f32bits(dinv[s]*ew)<<32)|src
__device__ ulonglong2 g_xw1v[(size_t)N_MAXC * 16];  // permuted xw1, 25.6MB
__device__ ulonglong2 g_xw2v[(size_t)N_MAXC * 8];   // xw2, 12.8MB
__device__ int        g_tickets[4];            // work-steal counters
__device__ int        g_count;
__device__ int        g_gen;

// ---- packed f32x2 helpers ----
__device__ __forceinline__ u64 ffma2(u64 a, u64 b, u64 c) {
    u64 d;
    asm("fma.rn.f32x2 %0, %1, %2, %3;" : "=l"(d) : "l"(a), "l"(b), "l"(c));
    return d;
}
__device__ __forceinline__ u64 dup2(u32 w) {
    u64 d;
    asm("mov.b64 %0, {%1, %1};" : "=l"(d) : "r"(w));
    return d;
}
__device__ __forceinline__ u64 pack2f(float x, float y) {
    u64 d;
    asm("mov.b64 %0, {%1, %2};" : "=l"(d) : "r"(__float_as_uint(x)), "r"(__float_as_uint(y)));
    return d;
}
__device__ __forceinline__ float2 unpk(u64 v) {
    float2 f;
    asm("mov.b64 {%0, %1}, %2;" : "=f"(f.x), "=f"(f.y) : "l"(v));
    return f;
}

// ---- grid barrier ----
__device__ __forceinline__ void gbar(int expect) {
    __syncthreads();
    if (threadIdx.x == 0) {
        __threadfence();
        int t = atomicAdd(&g_count, 1);
        if (t == NB - 1) {
            g_count = 0;
            __threadfence();
            *(volatile int*)&g_gen = expect;
        } else {
            while (*(volatile int*)&g_gen - expect < 0) {}
            __threadfence();
        }
    }
    __syncthreads();
}

__global__ void __launch_bounds__(BS, 4) mega(
    const float* __restrict__ x, const void* __restrict__ ei,
    const float* __restrict__ ew, const float* __restrict__ W1,
    const float* __restrict__ b1, const float* __restrict__ W2,
    const float* __restrict__ b2, float* __restrict__ out,
    int N, int E)
{
    __shared__ __align__(16) char s_mem[33792 + 4096];
    __shared__ int s_is64, s_tile;

    float* sX   = (float*)s_mem;                  // GEMM: [64][132] floats
    float* sW   = (float*)(s_mem + 33792);        // GEMM: [16][64] W chunk
    u64*   sEpi = (u64*)s_mem;                    // GEMM epi: [64][33] u64
    int*   s_scan = (int*)s_mem;                  // scans
    float* s_f  = (float*)s_mem;                  // SpMM: W2 8KB
    u64 (*s_ebuf)[32] = (u64(*)[32])(s_mem + 8192);
    float (*s_hrow)[HID] = (float(*)[HID])(s_mem + 8192 + 2048);

    const int tid = threadIdx.x;
    const int b   = blockIdx.x;
    const int gtid = b * BS + tid;
    const int wid = tid >> 5, lane = tid & 31;

    int ebase = 0;
    if (tid == 0) ebase = *(volatile int*)&g_gen;

    // ---------------- phase A: zero counters/tickets + i32/i64 detect -------
    for (int i = gtid; i < N; i += NT) { g_degcnt[i] = 0ull; g_cnt2[i] = 0; }
    if (gtid < 4) g_tickets[gtid] = 0;
    if (tid < 32) {
        const u32* u = (const u32*)ei;
        int cnt = E < 64 ? E : 64;
        bool nz = false;
        for (int j = tid; j < cnt; j += 32) nz |= (u[2 * j + 1] != 0u);
        u32 bl = __ballot_sync(0xffffffffu, nz);
        if (tid == 0) s_is64 = (bl == 0u) ? 1 : 0;
    }
    gbar(ebase + 1);
    const int is64 = s_is64;

    // ---------------- phase B: edge degree atomics + stolen GEMM tiles ------
    for (int e = gtid; e < E; e += NT) {
        int d = is64 ? (int)((const long long*)ei)[(size_t)E + e]
                     : ((const int*)ei)[(size_t)E + e];
        u64 add = (1ull << 42) | (u64)(u32)__float2uint_rn(ew[e] * 16777216.0f);
        atomicAdd(&g_degcnt[d], add);
    }
    __syncthreads();
    {
        const int ntiles = (N + 63) / 64;
        const int w8 = wid * 8;
        const int wb = 8 * (wid & 3) + (wid >> 2);
        for (;;) {
            if (tid == 0) s_tile = atomicAdd(&g_tickets[0], 1);
            __syncthreads();
            const int tile = s_tile;
            if (tile >= ntiles) break;
            const int row0 = tile * 64;
            for (int i = tid; i < 2048; i += BS) {
                int r = i >> 5, k4 = i & 31;
                float4 v = make_float4(0.f, 0.f, 0.f, 0.f);
                if (row0 + r < N)
                    v = ((const float4*)(x + (size_t)(row0 + r) * FIN1))[k4];
                *(float4*)&sX[r * 132 + 4 * k4] = v;
            }
            __syncthreads();

            u64 accA[4], accB[4];
#pragma unroll
            for (int j = 0; j < 4; j++) { accA[j] = 0ull; accB[j] = 0ull; }

            for (int c = 0; c < 8; c++) {
                {
                    int k = tid >> 4, c4 = tid & 15;
                    *(float4*)&sW[k * 64 + 4 * c4] =
                        ((const float4*)(W1 + (size_t)(c * 16 + k) * HID))[c4];
                }
                __syncthreads();
                const float4* xpA = (const float4*)&sX[lane * 132 + c * 16];
                const float4* xpB = (const float4*)&sX[(lane + 32) * 132 + c * 16];
#pragma unroll
                for (int k4 = 0; k4 < 4; k4++) {
                    float4 xa = xpA[k4];
                    float4 xb = xpB[k4];
                    float xsA[4] = {xa.x, xa.y, xa.z, xa.w};
                    float xsB[4] = {xb.x, xb.y, xb.z, xb.w};
#pragma unroll
                    for (int kk = 0; kk < 4; kk++) {
                        int k = k4 * 4 + kk;
                        ulonglong2 wv0 = *(const ulonglong2*)&sW[k * 64 + w8];
                        ulonglong2 wv1 = *(const ulonglong2*)&sW[k * 64 + w8 + 4];
                        u64 xA = dup2(__float_as_uint(xsA[kk]));
                        u64 xB = dup2(__float_as_uint(xsB[kk]));
                        accA[0] = ffma2(xA, wv0.x, accA[0]);
                        accA[1] = ffma2(xA, wv0.y, accA[1]);
                        accA[2] = ffma2(xA, wv1.x, accA[2]);
                        accA[3] = ffma2(xA, wv1.y, accA[3]);
                        accB[0] = ffma2(xB, wv0.x, accB[0]);
                        accB[1] = ffma2(xB, wv0.y, accB[1]);
                        accB[2] = ffma2(xB, wv1.x, accB[2]);
                        accB[3] = ffma2(xB, wv1.y, accB[3]);
                    }
                }
                __syncthreads();
            }
#pragma unroll
            for (int p = 0; p < 4; p++) {
                sEpi[lane * 33 + wb + 2 * p] = accA[p];
                sEpi[(lane + 32) * 33 + wb + 2 * p] = accB[p];
            }
            __syncthreads();
            u64* xw1u = (u64*)g_xw1v;
            for (int i = tid; i < 2048; i += BS) {
                int r = i >> 5, s = i & 31;
                if (row0 + r < N)
                    xw1u[(size_t)(row0 + r) * 32 + s] = sEpi[r * 33 + s];
            }
            __syncthreads();
        }
    }
    gbar(ebase + 2);

    // ---------------- phase C: dinv + per-block count scan ------------------
    const int CH = (N + NB - 1) / NB;
    const int rbase = b * CH;
    const int rend = (rbase + CH < N) ? (rbase + CH) : N;
    const int r0 = rbase + tid;
    int c0 = 0;
    if (r0 < rend) {
        u64 pc = g_degcnt[r0];
        c0 = (int)(pc >> 42);
        g_dinv[r0] = rsqrtf(1.0f + (float)(pc & ((1ull << 42) - 1)) * (1.0f / 16777216.0f));
    }
    s_scan[tid] = c0;
    __syncthreads();
    for (int off = 1; off < BS; off <<= 1) {
        int a = (tid >= off) ? s_scan[tid - off] : 0;
        __syncthreads();
        s_scan[tid] += a;
        __syncthreads();
    }
    int ex0 = s_scan[tid] - c0;
    if (r0 < rend) g_rowptr[r0] = ex0;
    if (tid == BS - 1) g_bsums[b] = s_scan[BS - 1];
    gbar(ebase + 3);

    // ---------------- phase DE: block offsets + finalize rowptr -------------
    {
        int v = 0;
        for (int j = tid; j < b; j += BS) v += g_bsums[j];
        __syncthreads();
        s_scan[tid] = v;
        __syncthreads();
        for (int off = BS / 2; off > 0; off >>= 1) {
            if (tid < off) s_scan[tid] += s_scan[tid + off];
            __syncthreads();
        }
        int off_b = s_scan[0];
        if (r0 < rend) g_rowptr[r0] += off_b;
        if (gtid == 0) g_rowptr[N] = E;
    }
    gbar(ebase + 4);

    // ---------------- phase F: fill CSR (w' = dinv[src]*ew) -----------------
    for (int e = gtid; e < E; e += NT) {
        int s, d;
        if (is64) {
            const long long* p = (const long long*)ei;
            s = (int)p[e]; d = (int)p[(size_t)E + e];
        } else {
            const int* p = (const int*)ei;
            s = p[e]; d = p[(size_t)E + e];
        }
        float wp = g_dinv[s] * ew[e];
        int slot = g_rowptr[d] + atomicAdd(&g_cnt2[d], 1);
        g_csr[slot] = ((u64)__float_as_uint(wp) << 32) | (u32)s;
    }
    gbar(ebase + 5);

    // ---------------- phase G: SpMM1 (stolen 8-row chunks) + fused h@W2 -----
    for (int i = tid; i < HID * CLS; i += BS) s_f[i] = W2[i];
    __syncthreads();
    const int slot = lane >> 4, cc = lane & 15;
    float b1a = b1[2 * cc], b1b = b1[2 * cc + 1];
    float b1c = b1[32 + 2 * cc], b1d = b1[33 + 2 * cc];
    u64* buf = s_ebuf[wid];
    for (;;) {
        int chunk;
        if (lane == 0) chunk = atomicAdd(&g_tickets[1], 1);
        chunk = __shfl_sync(0xffffffffu, chunk, 0);
        int row0c = chunk * 8;
        if (row0c >= N) break;
        int row1c = row0c + 8 < N ? row0c + 8 : N;
        for (int row = row0c; row < row1c; row++) {
            float dn = g_dinv[row];
            u64 acc01 = 0ull, acc23 = 0ull;
            if (slot == 0) {
                float4 sv = ((const float4*)(g_xw1v + (size_t)row * 16))[cc];
                acc01 = pack2f(dn * sv.x, dn * sv.y);
                acc23 = pack2f(dn * sv.z, dn * sv.w);
            }
            int p = g_rowptr[row], pe = g_rowptr[row + 1];
            while (p < pe) {
                int m = pe - p; if (m > 32) m = 32;
                buf[lane] = (lane < m) ? g_csr[p + lane] : 0ull;
                __syncwarp();
                int pairs = (m + 1) >> 1;
                int t = 0;
                for (; t + 4 <= pairs; t += 4) {
                    u64 q0 = buf[2 * t + slot],     q1 = buf[2 * t + 2 + slot];
                    u64 q2 = buf[2 * t + 4 + slot], q3 = buf[2 * t + 6 + slot];
                    ulonglong2 v0 = g_xw1v[(size_t)(u32)q0 * 16 + cc];
                    ulonglong2 v1 = g_xw1v[(size_t)(u32)q1 * 16 + cc];
                    ulonglong2 v2 = g_xw1v[(size_t)(u32)q2 * 16 + cc];
                    ulonglong2 v3 = g_xw1v[(size_t)(u32)q3 * 16 + cc];
                    u64 w0 = dup2((u32)(q0 >> 32)), w1 = dup2((u32)(q1 >> 32));
                    u64 w2 = dup2((u32)(q2 >> 32)), w3 = dup2((u32)(q3 >> 32));
                    acc01 = ffma2(w0, v0.x, acc01); acc23 = ffma2(w0, v0.y, acc23);
                    acc01 = ffma2(w1, v1.x, acc01); acc23 = ffma2(w1, v1.y, acc23);
                    acc01 = ffma2(w2, v2.x, acc01); acc23 = ffma2(w2, v2.y, acc23);
                    acc01 = ffma2(w3, v3.x, acc01); acc23 = ffma2(w3, v3.y, acc23);
                }
                for (; t < pairs; t++) {
                    u64 q0 = buf[2 * t + slot];
                    ulonglong2 v0 = g_xw1v[(size_t)(u32)q0 * 16 + cc];
                    u64 w0 = dup2((u32)(q0 >> 32));
                    acc01 = ffma2(w0, v0.x, acc01); acc23 = ffma2(w0, v0.y, acc23);
                }
                __syncwarp();
                p += 32;
            }
            float2 a01 = unpk(acc01), a23 = unpk(acc23);
            a01.x += __shfl_xor_sync(0xffffffffu, a01.x, 16);
            a01.y += __shfl_xor_sync(0xffffffffu, a01.y, 16);
            a23.x += __shfl_xor_sync(0xffffffffu, a23.x, 16);
            a23.y += __shfl_xor_sync(0xffffffffu, a23.y, 16);
            float hx = fmaxf(dn * a01.x + b1a, 0.0f);
            float hy = fmaxf(dn * a01.y + b1b, 0.0f);
            float hz = fmaxf(dn * a23.x + b1c, 0.0f);
            float hw = fmaxf(dn * a23.y + b1d, 0.0f);
            if (slot == 0)
                ((float4*)s_hrow[wid])[cc] = make_float4(hx, hy, hz, hw);
            __syncwarp();
            float acc = 0.0f;
            const float4* hr = (const float4*)s_hrow[wid];
#pragma unroll
            for (int c2 = 0; c2 < 16; c2++) {
                float4 hv = hr[c2];
                acc = fmaf(hv.x, s_f[(2 * c2) * CLS + lane], acc);
                acc = fmaf(hv.y, s_f[(2 * c2 + 1) * CLS + lane], acc);
                acc = fmaf(hv.z, s_f[(32 + 2 * c2) * CLS + lane], acc);
                acc = fmaf(hv.w, s_f[(33 + 2 * c2) * CLS + lane], acc);
            }
            ((float*)(g_xw2v + (size_t)row * 8))[lane] = acc;
            __syncwarp();
        }
    }
    gbar(ebase + 6);

    // ---------------- phase H: SpMM2 (stolen 8-row chunks) -> out -----------
    {
        float2 b2v = ((const float2*)b2)[cc];
        const u64* X2 = (const u64*)g_xw2v;
        for (;;) {
            int chunk;
            if (lane == 0) chunk = atomicAdd(&g_tickets[2], 1);
            chunk = __shfl_sync(0xffffffffu, chunk, 0);
            int row0c = chunk * 8;
            if (row0c >= N) break;
            int row1c = row0c + 8 < N ? row0c + 8 : N;
            for (int row = row0c; row < row1c; row++) {
                float dn = g_dinv[row];
                u64 acc = 0ull;
                if (slot == 0) {
                    float2 sv = ((const float2*)(g_xw2v + (size_t)row * 8))[cc];
                    acc = pack2f(dn * sv.x, dn * sv.y);
                }
                int p = g_rowptr[row], pe = g_rowptr[row + 1];
                while (p < pe) {
                    int m = pe - p; if (m > 32) m = 32;
                    buf[lane] = (lane < m) ? g_csr[p + lane] : 0ull;
                    __syncwarp();
                    int pairs = (m + 1) >> 1;
                    int t = 0;
                    for (; t + 4 <= pairs; t += 4) {
                        u64 q0 = buf[2 * t + slot],     q1 = buf[2 * t + 2 + slot];
                        u64 q2 = buf[2 * t + 4 + slot], q3 = buf[2 * t + 6 + slot];
                        u64 v0 = X2[(size_t)(u32)q0 * 16 + cc];
                        u64 v1 = X2[(size_t)(u32)q1 * 16 + cc];
                        u64 v2 = X2[(size_t)(u32)q2 * 16 + cc];
                        u64 v3 = X2[(size_t)(u32)q3 * 16 + cc];
                        acc = ffma2(dup2((u32)(q0 >> 32)), v0, acc);
                        acc = ffma2(dup2((u32)(q1 >> 32)), v1, acc);
                        acc = ffma2(dup2((u32)(q2 >> 32)), v2, acc);
                        acc = ffma2(dup2((u32)(q3 >> 32)), v3, acc);
                    }
                    for (; t < pairs; t++) {
                        u64 q0 = buf[2 * t + slot];
                        acc = ffma2(dup2((u32)(q0 >> 32)),
                                    X2[(size_t)(u32)q0 * 16 + cc], acc);
                    }
                    __syncwarp();
                    p += 32;
                }
                float2 a = unpk(acc);
                a.x += __shfl_xor_sync(0xffffffffu, a.x, 16);
                a.y += __shfl_xor_sync(0xffffffffu, a.y, 16);
                if (slot == 0)
                    ((float2*)(out + (size_t)row * CLS))[cc] =
                        make_float2(dn * a.x + b2v.x, dn * a.y + b2v.y);
            }
        }
    }
}

// ---------------------------------------------------------------------------
extern "C" void kernel_launch(void* const* d_in, const int* in_sizes, int n_in,
                              void* d_out, int out_size) {
    const float* x  = (const float*)d_in[0];
    const void*  ei = d_in[1];
    const float* ew = (const float*)d_in[2];
    const float* W1 = (const float*)d_in[3];
    const float* b1 = (const float*)d_in[4];
    const float* W2 = (const float*)d_in[5];
    const float* b2 = (const float*)d_in[6];
    float* out = (float*)d_out;

    int E = in_sizes[2];
    int N = in_sizes[0] / FIN1;
    if (N > N_MAXC) N = N_MAXC;
    if (E > E_MAXC) E = E_MAXC;

    mega<<<NB, BS>>>(x, ei, ew, W1, b1, W2, b2, out, N, E);
}

// round 9
// speedup vs baseline: 1.6065x; 1.0488x over previous
#include <cuda_runtime.h>
#include <stdint.h>

// ---------------------------------------------------------------------------
// 2-layer GCN, single persistent kernel. Round 9:
//  - rows prescaled by dinv -> CSR weight = ew only (no dinv gather in fill)
//  - fill slot precomputed from phase-B atomic return (no fill atomics)
//  - fill + GEMM merged in one phase; SpMM1 MLP=8; f32x2 projection
// ---------------------------------------------------------------------------

#define N_MAXC  100000
#define E_MAXC  1700000
#define FIN1    128
#define HID     64
#define CLS     32
#define NB      512
#define BS      256
#define NT      (NB * BS)

typedef unsigned long long u64;
typedef unsigned int u32;

// ---- device scratch ----
__device__ u64        g_degcnt[N_MAXC];        // (count<<42) | fixed24(sum ew)
__device__ u32        g_slot[E_MAXC];          // per-edge slot within dst bucket
__device__ int        g_rowptr[N_MAXC + 1];
__device__ float      g_dinv[N_MAXC];
__device__ int        g_bsums[NB];
__device__ u64        g_csr[E_MAXC];           // (f32bits(ew)<<32)|src
__device__ ulonglong2 g_xw1v[(size_t)N_MAXC * 16];  // prescaled permuted xw1
__device__ ulonglong2 g_xw2v[(size_t)N_MAXC * 8];   // prescaled xw2
__device__ int        g_tickets[4];
__device__ int        g_count;
__device__ int        g_gen;

// ---- packed f32x2 helpers ----
__device__ __forceinline__ u64 ffma2(u64 a, u64 b, u64 c) {
    u64 d;
    asm("fma.rn.f32x2 %0, %1, %2, %3;" : "=l"(d) : "l"(a), "l"(b), "l"(c));
    return d;
}
__device__ __forceinline__ u64 dup2(u32 w) {
    u64 d;
    asm("mov.b64 %0, {%1, %1};" : "=l"(d) : "r"(w));
    return d;
}
__device__ __forceinline__ u64 pack2f(float x, float y) {
    u64 d;
    asm("mov.b64 %0, {%1, %2};" : "=l"(d) : "r"(__float_as_uint(x)), "r"(__float_as_uint(y)));
    return d;
}
__device__ __forceinline__ float2 unpk(u64 v) {
    float2 f;
    asm("mov.b64 {%0, %1}, %2;" : "=f"(f.x), "=f"(f.y) : "l"(v));
    return f;
}

// ---- grid barrier ----
__device__ __forceinline__ void gbar(int expect) {
    __syncthreads();
    if (threadIdx.x == 0) {
        __threadfence();
        int t = atomicAdd(&g_count, 1);
        if (t == NB - 1) {
            g_count = 0;
            __threadfence();
            *(volatile int*)&g_gen = expect;
        } else {
            while (*(volatile int*)&g_gen - expect < 0) {}
            __threadfence();
        }
    }
    __syncthreads();
}

__global__ void __launch_bounds__(BS, 4) mega(
    const float* __restrict__ x, const void* __restrict__ ei,
    const float* __restrict__ ew, const float* __restrict__ W1,
    const float* __restrict__ b1, const float* __restrict__ W2,
    const float* __restrict__ b2, float* __restrict__ out,
    int N, int E)
{
    __shared__ __align__(16) char s_mem[33792 + 4096];
    __shared__ int s_is64, s_tile;

    float* sX   = (float*)s_mem;                  // GEMM: [64][132]
    float* sW   = (float*)(s_mem + 33792);        // GEMM: [16][64]
    u64*   sEpi = (u64*)s_mem;                    // GEMM epi: [64][33] u64
    int*   s_scan = (int*)s_mem;
    u64*   s_w2a = (u64*)s_mem;                   // proj pairs lo (16*32 u64)
    u64*   s_w2b = (u64*)(s_mem + 4096);          // proj pairs hi
    u64 (*s_ebuf)[32] = (u64(*)[32])(s_mem + 8192);
    float (*s_hrow)[HID] = (float(*)[HID])(s_mem + 8192 + 2048);

    const int tid = threadIdx.x;
    const int b   = blockIdx.x;
    const int gtid = b * BS + tid;
    const int wid = tid >> 5, lane = tid & 31;

    int ebase = 0;
    if (tid == 0) ebase = *(volatile int*)&g_gen;

    // ---------------- phase A: zero counters/tickets + i32/i64 detect -------
    for (int i = gtid; i < N; i += NT) g_degcnt[i] = 0ull;
    if (gtid < 4) g_tickets[gtid] = 0;
    if (tid < 32) {
        const u32* u = (const u32*)ei;
        int cnt = E < 64 ? E : 64;
        bool nz = false;
        for (int j = tid; j < cnt; j += 32) nz |= (u[2 * j + 1] != 0u);
        u32 bl = __ballot_sync(0xffffffffu, nz);
        if (tid == 0) s_is64 = (bl == 0u) ? 1 : 0;
    }
    gbar(ebase + 1);
    const int is64 = s_is64;

    // ---------------- phase B: edge degree atomics, record slots ------------
    for (int e = gtid; e < E; e += NT) {
        int d = is64 ? (int)((const long long*)ei)[(size_t)E + e]
                     : ((const int*)ei)[(size_t)E + e];
        u64 add = (1ull << 42) | (u64)(u32)__float2uint_rn(ew[e] * 16777216.0f);
        u64 old = atomicAdd(&g_degcnt[d], add);
        g_slot[e] = (u32)(old >> 42);
    }
    gbar(ebase + 2);

    // ---------------- phase C: dinv + per-block count scan ------------------
    const int CH = (N + NB - 1) / NB;
    const int rbase = b * CH;
    const int rend = (rbase + CH < N) ? (rbase + CH) : N;
    const int r0 = rbase + tid;
    int c0 = 0;
    if (r0 < rend) {
        u64 pc = g_degcnt[r0];
        c0 = (int)(pc >> 42);
        g_dinv[r0] = rsqrtf(1.0f + (float)(pc & ((1ull << 42) - 1)) * (1.0f / 16777216.0f));
    }
    s_scan[tid] = c0;
    __syncthreads();
    for (int off = 1; off < BS; off <<= 1) {
        int a = (tid >= off) ? s_scan[tid - off] : 0;
        __syncthreads();
        s_scan[tid] += a;
        __syncthreads();
    }
    int ex0 = s_scan[tid] - c0;
    if (r0 < rend) g_rowptr[r0] = ex0;
    if (tid == BS - 1) g_bsums[b] = s_scan[BS - 1];
    gbar(ebase + 3);

    // ---------------- phase DE: block offsets + finalize rowptr -------------
    {
        int v = 0;
        for (int j = tid; j < b; j += BS) v += g_bsums[j];
        __syncthreads();
        s_scan[tid] = v;
        __syncthreads();
        for (int off = BS / 2; off > 0; off >>= 1) {
            if (tid < off) s_scan[tid] += s_scan[tid + off];
            __syncthreads();
        }
        int off_b = s_scan[0];
        if (r0 < rend) g_rowptr[r0] += off_b;
        if (gtid == 0) g_rowptr[N] = E;
    }
    gbar(ebase + 4);

    // ---------------- phase F: fill CSR (no atomics) + GEMM1 (prescaled) ----
    for (int e = gtid; e < E; e += NT) {
        int s, d;
        if (is64) {
            const long long* p = (const long long*)ei;
            s = (int)p[e]; d = (int)p[(size_t)E + e];
        } else {
            const int* p = (const int*)ei;
            s = p[e]; d = p[(size_t)E + e];
        }
        int slot = g_rowptr[d] + (int)g_slot[e];
        g_csr[slot] = ((u64)__float_as_uint(ew[e]) << 32) | (u32)s;
    }
    __syncthreads();
    {
        const int ntiles = (N + 63) / 64;
        const int w8 = wid * 8;
        const int wb = 8 * (wid & 3) + (wid >> 2);
        for (;;) {
            if (tid == 0) s_tile = atomicAdd(&g_tickets[0], 1);
            __syncthreads();
            const int tile = s_tile;
            if (tile >= ntiles) break;
            const int row0 = tile * 64;
            for (int i = tid; i < 2048; i += BS) {
                int r = i >> 5, k4 = i & 31;
                float4 v = make_float4(0.f, 0.f, 0.f, 0.f);
                if (row0 + r < N)
                    v = ((const float4*)(x + (size_t)(row0 + r) * FIN1))[k4];
                *(float4*)&sX[r * 132 + 4 * k4] = v;
            }
            __syncthreads();

            u64 accA[4], accB[4];
#pragma unroll
            for (int j = 0; j < 4; j++) { accA[j] = 0ull; accB[j] = 0ull; }

            for (int c = 0; c < 8; c++) {
                {
                    int k = tid >> 4, c4 = tid & 15;
                    *(float4*)&sW[k * 64 + 4 * c4] =
                        ((const float4*)(W1 + (size_t)(c * 16 + k) * HID))[c4];
                }
                __syncthreads();
                const float4* xpA = (const float4*)&sX[lane * 132 + c * 16];
                const float4* xpB = (const float4*)&sX[(lane + 32) * 132 + c * 16];
#pragma unroll
                for (int k4 = 0; k4 < 4; k4++) {
                    float4 xa = xpA[k4];
                    float4 xb = xpB[k4];
                    float xsA[4] = {xa.x, xa.y, xa.z, xa.w};
                    float xsB[4] = {xb.x, xb.y, xb.z, xb.w};
#pragma unroll
                    for (int kk = 0; kk < 4; kk++) {
                        int k = k4 * 4 + kk;
                        ulonglong2 wv0 = *(const ulonglong2*)&sW[k * 64 + w8];
                        ulonglong2 wv1 = *(const ulonglong2*)&sW[k * 64 + w8 + 4];
                        u64 xA = dup2(__float_as_uint(xsA[kk]));
                        u64 xB = dup2(__float_as_uint(xsB[kk]));
                        accA[0] = ffma2(xA, wv0.x, accA[0]);
                        accA[1] = ffma2(xA, wv0.y, accA[1]);
                        accA[2] = ffma2(xA, wv1.x, accA[2]);
                        accA[3] = ffma2(xA, wv1.y, accA[3]);
                        accB[0] = ffma2(xB, wv0.x, accB[0]);
                        accB[1] = ffma2(xB, wv0.y, accB[1]);
                        accB[2] = ffma2(xB, wv1.x, accB[2]);
                        accB[3] = ffma2(xB, wv1.y, accB[3]);
                    }
                }
                __syncthreads();
            }
#pragma unroll
            for (int p = 0; p < 4; p++) {
                sEpi[lane * 33 + wb + 2 * p] = accA[p];
                sEpi[(lane + 32) * 33 + wb + 2 * p] = accB[p];
            }
            __syncthreads();
            u64* xw1u = (u64*)g_xw1v;
            for (int i = tid; i < 2048; i += BS) {
                int r = i >> 5, s = i & 31;
                int row = row0 + r;
                if (row < N) {
                    u64 dnr = dup2(__float_as_uint(g_dinv[row]));
                    xw1u[(size_t)row * 32 + s] = ffma2(dnr, sEpi[r * 33 + s], 0ull);
                }
            }
            __syncthreads();
        }
    }
    gbar(ebase + 5);

    // ---------------- phase G: SpMM1 (MLP=8) + f32x2 projection -------------
    for (int i = tid; i < HID * CLS; i += BS) {
        int k = i >> 5, c = i & 31;
        float v = W2[k * CLS + c];
        int c2 = (k & 31) >> 1;
        float* base = (float*)((k >= 32) ? s_w2b : s_w2a);
        base[(c2 * 32 + c) * 2 + (k & 1)] = v;
    }
    __syncthreads();
    const int slot = lane >> 4, cc = lane & 15;
    float b1a = b1[2 * cc], b1b = b1[2 * cc + 1];
    float b1c = b1[32 + 2 * cc], b1d = b1[33 + 2 * cc];
    u64* buf = s_ebuf[wid];
    const u32* bufw = (const u32*)buf;
    for (;;) {
        int chunk;
        if (lane == 0) chunk = atomicAdd(&g_tickets[1], 1);
        chunk = __shfl_sync(0xffffffffu, chunk, 0);
        int row0c = chunk * 8;
        if (row0c >= N) break;
        int row1c = row0c + 8 < N ? row0c + 8 : N;
        for (int row = row0c; row < row1c; row++) {
            float dn = g_dinv[row];
            u64 acc01 = 0ull, acc23 = 0ull;
            if (slot == 0) {
                ulonglong2 sv = g_xw1v[(size_t)row * 16 + cc];
                acc01 = sv.x; acc23 = sv.y;           // prescaled self row
            }
            int p = g_rowptr[row], pe = g_rowptr[row + 1];
            while (p < pe) {
                int m = pe - p; if (m > 32) m = 32;
                buf[lane] = (lane < m) ? g_csr[p + lane] : 0ull;
                __syncwarp();
                int pairs = (m + 1) >> 1;
                int t = 0;
                for (; t + 8 <= pairs; t += 8) {
                    ulonglong2 v[8];
#pragma unroll
                    for (int i = 0; i < 8; i++) {
                        u32 src = bufw[(2 * (t + i) + slot) * 2];
                        v[i] = g_xw1v[(size_t)src * 16 + cc];
                    }
#pragma unroll
                    for (int i = 0; i < 8; i++) {
                        u64 w = dup2(bufw[(2 * (t + i) + slot) * 2 + 1]);
                        acc01 = ffma2(w, v[i].x, acc01);
                        acc23 = ffma2(w, v[i].y, acc23);
                    }
                }
                for (; t < pairs; t++) {
                    u32 src = bufw[(2 * t + slot) * 2];
                    u64 w = dup2(bufw[(2 * t + slot) * 2 + 1]);
                    ulonglong2 v0 = g_xw1v[(size_t)src * 16 + cc];
                    acc01 = ffma2(w, v0.x, acc01);
                    acc23 = ffma2(w, v0.y, acc23);
                }
                __syncwarp();
                p += 32;
            }
            float2 a01 = unpk(acc01), a23 = unpk(acc23);
            a01.x += __shfl_xor_sync(0xffffffffu, a01.x, 16);
            a01.y += __shfl_xor_sync(0xffffffffu, a01.y, 16);
            a23.x += __shfl_xor_sync(0xffffffffu, a23.x, 16);
            a23.y += __shfl_xor_sync(0xffffffffu, a23.y, 16);
            float hx = fmaxf(dn * a01.x + b1a, 0.0f);
            float hy = fmaxf(dn * a01.y + b1b, 0.0f);
            float hz = fmaxf(dn * a23.x + b1c, 0.0f);
            float hw = fmaxf(dn * a23.y + b1d, 0.0f);
            if (slot == 0)
                ((float4*)s_hrow[wid])[cc] = make_float4(hx, hy, hz, hw);
            __syncwarp();
            // projection (f32x2): out col = lane
            u64 accp = 0ull;
            const float4* hr = (const float4*)s_hrow[wid];
#pragma unroll
            for (int c2 = 0; c2 < 16; c2++) {
                float4 hv = hr[c2];
                accp = ffma2(pack2f(hv.x, hv.y), s_w2a[c2 * 32 + lane], accp);
                accp = ffma2(pack2f(hv.z, hv.w), s_w2b[c2 * 32 + lane], accp);
            }
            float2 ap = unpk(accp);
            ((float*)(g_xw2v + (size_t)row * 8))[lane] = dn * (ap.x + ap.y);
            __syncwarp();
        }
    }
    gbar(ebase + 6);

    // ---------------- phase H: SpMM2 (MLP=8) -> out -------------------------
    {
        float2 b2v = ((const float2*)b2)[cc];
        const u64* X2 = (const u64*)g_xw2v;
        for (;;) {
            int chunk;
            if (lane == 0) chunk = atomicAdd(&g_tickets[2], 1);
            chunk = __shfl_sync(0xffffffffu, chunk, 0);
            int row0c = chunk * 8;
            if (row0c >= N) break;
            int row1c = row0c + 8 < N ? row0c + 8 : N;
            for (int row = row0c; row < row1c; row++) {
                float dn = g_dinv[row];
                u64 acc = 0ull;
                if (slot == 0) acc = X2[(size_t)row * 16 + cc];   // prescaled
                int p = g_rowptr[row], pe = g_rowptr[row + 1];
                while (p < pe) {
                    int m = pe - p; if (m > 32) m = 32;
                    buf[lane] = (lane < m) ? g_csr[p + lane] : 0ull;
                    __syncwarp();
                    int pairs = (m + 1) >> 1;
                    int t = 0;
                    for (; t + 8 <= pairs; t += 8) {
                        u64 v[8];
#pragma unroll
                        for (int i = 0; i < 8; i++) {
                            u32 src = bufw[(2 * (t + i) + slot) * 2];
                            v[i] = X2[(size_t)src * 16 + cc];
                        }
#pragma unroll
                        for (int i = 0; i < 8; i++) {
                            u64 w = dup2(bufw[(2 * (t + i) + slot) * 2 + 1]);
                            acc = ffma2(w, v[i], acc);
                        }
                    }
                    for (; t < pairs; t++) {
                        u32 src = bufw[(2 * t + slot) * 2];
                        u64 w = dup2(bufw[(2 * t + slot) * 2 + 1]);
                        acc = ffma2(w, X2[(size_t)src * 16 + cc], acc);
                    }
                    __syncwarp();
                    p += 32;
                }
                float2 a = unpk(acc);
                a.x += __shfl_xor_sync(0xffffffffu, a.x, 16);
                a.y += __shfl_xor_sync(0xffffffffu, a.y, 16);
                if (slot == 0)
                    ((float2*)(out + (size_t)row * CLS))[cc] =
                        make_float2(dn * a.x + b2v.x, dn * a.y + b2v.y);
            }
        }
    }
}

// ---------------------------------------------------------------------------
extern "C" void kernel_launch(void* const* d_in, const int* in_sizes, int n_in,
                              void* d_out, int out_size) {
    const float* x  = (const float*)d_in[0];
    const void*  ei = d_in[1];
    const float* ew = (const float*)d_in[2];
    const float* W1 = (const float*)d_in[3];
    const float* b1 = (const float*)d_in[4];
    const float* W2 = (const float*)d_in[5];
    const float* b2 = (const float*)d_in[6];
    float* out = (float*)d_out;

    int E = in_sizes[2];
    int N = in_sizes[0] / FIN1;
    if (N > N_MAXC) N = N_MAXC;
    if (E > E_MAXC) E = E_MAXC;

    mega<<<NB, BS>>>(x, ei, ew, W1, b1, W2, b2, out, N, E);
}

// round 10
// speedup vs baseline: 1.6085x; 1.0013x over previous
#include <cuda_runtime.h>
#include <stdint.h>

// ---------------------------------------------------------------------------
// 2-layer GCN, single persistent kernel. Round 10: serialization diet.
// 5 phases / 5 barriers (was 8/6): tail re-zero + monotonic tickets,
// GEMM overlapped with edge atomics, local block-prefix replaces DE phase,
// streaming dinv prescale pass. SpMM math identical to round 9.
// ---------------------------------------------------------------------------

#define N_MAXC  100000
#define E_MAXC  1700000
#define FIN1    128
#define HID     64
#define CLS     32
#define NB      512
#define BS      256
#define NT      (NB * BS)

typedef unsigned long long u64;
typedef unsigned int u32;

// ---- device scratch ----
__device__ u64        g_degcnt[N_MAXC];        // (count<<42)|fixed24(sum ew); 0 at entry
__device__ u32        g_slot[E_MAXC];
__device__ int        g_rowptr[N_MAXC + 1];    // PRE-offset (intra-chunk exclusive)
__device__ float      g_dinv[N_MAXC];
__device__ int        g_bsums[NB];
__device__ u64        g_csr[E_MAXC];           // (f32bits(ew)<<32)|src
__device__ ulonglong2 g_xw1v[(size_t)N_MAXC * 16];  // permuted xw1 (prescaled in F)
__device__ ulonglong2 g_xw2v[(size_t)N_MAXC * 8];
__device__ int        g_tickets[4];            // monotonic across runs
__device__ int        g_count;
__device__ int        g_gen;

// ---- packed f32x2 helpers ----
__device__ __forceinline__ u64 ffma2(u64 a, u64 b, u64 c) {
    u64 d;
    asm("fma.rn.f32x2 %0, %1, %2, %3;" : "=l"(d) : "l"(a), "l"(b), "l"(c));
    return d;
}
__device__ __forceinline__ u64 dup2(u32 w) {
    u64 d;
    asm("mov.b64 %0, {%1, %1};" : "=l"(d) : "r"(w));
    return d;
}
__device__ __forceinline__ u64 pack2f(float x, float y) {
    u64 d;
    asm("mov.b64 %0, {%1, %2};" : "=l"(d) : "r"(__float_as_uint(x)), "r"(__float_as_uint(y)));
    return d;
}
__device__ __forceinline__ float2 unpk(u64 v) {
    float2 f;
    asm("mov.b64 {%0, %1}, %2;" : "=f"(f.x), "=f"(f.y) : "l"(v));
    return f;
}

// ---- grid barrier ----
__device__ __forceinline__ void gbar(int expect) {
    __syncthreads();
    if (threadIdx.x == 0) {
        __threadfence();
        int t = atomicAdd(&g_count, 1);
        if (t == NB - 1) {
            g_count = 0;
            __threadfence();
            *(volatile int*)&g_gen = expect;
        } else {
            while (*(volatile int*)&g_gen - expect < 0) {}
            __threadfence();
        }
    }
    __syncthreads();
}

__global__ void __launch_bounds__(BS, 4) mega(
    const float* __restrict__ x, const void* __restrict__ ei,
    const float* __restrict__ ew, const float* __restrict__ W1,
    const float* __restrict__ b1, const float* __restrict__ W2,
    const float* __restrict__ b2, float* __restrict__ out,
    int N, int E)
{
    __shared__ __align__(16) char s_mem[33792 + 4096];
    __shared__ int s_is64, s_tile, s_tb0, s_tb1, s_tb2;

    float* sX   = (float*)s_mem;                  // GEMM: [64][132]
    float* sW   = (float*)(s_mem + 33792);        // GEMM: [16][64]
    u64*   sEpi = (u64*)s_mem;                    // GEMM epi: [64][33] u64
    int*   s_scan = (int*)s_mem;                  // C scan (1KB)
    u64*   s_w2a = (u64*)s_mem;                   // proj pairs lo
    u64*   s_w2b = (u64*)(s_mem + 4096);          // proj pairs hi
    u64 (*s_ebuf)[32] = (u64(*)[32])(s_mem + 8192);
    float (*s_hrow)[HID] = (float(*)[HID])(s_mem + 8192 + 2048);
    int*   s_pfx = (int*)(s_mem + 16384);         // block prefix, persists F..H

    const int tid = threadIdx.x;
    const int b   = blockIdx.x;
    const int gtid = b * BS + tid;
    const int wid = tid >> 5, lane = tid & 31;

    // ---------------- entry: bases + i32/i64 detect (block-local) -----------
    int ebase = 0;
    if (tid == 0) {
        ebase = *(volatile int*)&g_gen;
        s_tb0 = *(volatile int*)&g_tickets[0];
        s_tb1 = *(volatile int*)&g_tickets[1];
        s_tb2 = *(volatile int*)&g_tickets[2];
    }
    if (tid < 32) {
        const u32* u = (const u32*)ei;
        int cnt = E < 64 ? E : 64;
        bool nz = false;
        for (int j = tid; j < cnt; j += 32) nz |= (u[2 * j + 1] != 0u);
        u32 bl = __ballot_sync(0xffffffffu, nz);
        if (tid == 0) s_is64 = (bl == 0u) ? 1 : 0;
    }
    gbar(ebase + 1);          // protects ticket bases before any steal
    const int is64 = s_is64;

    // ---------------- phase B: edge atomics+slots OVERLAPPED with GEMM ------
    for (int e = gtid; e < E; e += NT) {
        int d = is64 ? (int)((const long long*)ei)[(size_t)E + e]
                     : ((const int*)ei)[(size_t)E + e];
        u64 add = (1ull << 42) | (u64)(u32)__float2uint_rn(ew[e] * 16777216.0f);
        u64 old = atomicAdd(&g_degcnt[d], add);
        g_slot[e] = (u32)(old >> 42);
    }
    {
        const int ntiles = (N + 63) / 64;
        const int w8 = wid * 8;
        const int wb = 8 * (wid & 3) + (wid >> 2);
        for (;;) {
            if (tid == 0) s_tile = atomicAdd(&g_tickets[0], 1) - s_tb0;
            __syncthreads();
            const int tile = s_tile;
            if (tile >= ntiles) break;
            const int row0 = tile * 64;
            for (int i = tid; i < 2048; i += BS) {
                int r = i >> 5, k4 = i & 31;
                float4 v = make_float4(0.f, 0.f, 0.f, 0.f);
                if (row0 + r < N)
                    v = ((const float4*)(x + (size_t)(row0 + r) * FIN1))[k4];
                *(float4*)&sX[r * 132 + 4 * k4] = v;
            }
            __syncthreads();

            u64 accA[4], accB[4];
#pragma unroll
            for (int j = 0; j < 4; j++) { accA[j] = 0ull; accB[j] = 0ull; }

            for (int c = 0; c < 8; c++) {
                {
                    int k = tid >> 4, c4 = tid & 15;
                    *(float4*)&sW[k * 64 + 4 * c4] =
                        ((const float4*)(W1 + (size_t)(c * 16 + k) * HID))[c4];
                }
                __syncthreads();
                const float4* xpA = (const float4*)&sX[lane * 132 + c * 16];
                const float4* xpB = (const float4*)&sX[(lane + 32) * 132 + c * 16];
#pragma unroll
                for (int k4 = 0; k4 < 4; k4++) {
                    float4 xa = xpA[k4];
                    float4 xb = xpB[k4];
                    float xsA[4] = {xa.x, xa.y, xa.z, xa.w};
                    float xsB[4] = {xb.x, xb.y, xb.z, xb.w};
#pragma unroll
                    for (int kk = 0; kk < 4; kk++) {
                        int k = k4 * 4 + kk;
                        ulonglong2 wv0 = *(const ulonglong2*)&sW[k * 64 + w8];
                        ulonglong2 wv1 = *(const ulonglong2*)&sW[k * 64 + w8 + 4];
                        u64 xA = dup2(__float_as_uint(xsA[kk]));
                        u64 xB = dup2(__float_as_uint(xsB[kk]));
                        accA[0] = ffma2(xA, wv0.x, accA[0]);
                        accA[1] = ffma2(xA, wv0.y, accA[1]);
                        accA[2] = ffma2(xA, wv1.x, accA[2]);
                        accA[3] = ffma2(xA, wv1.y, accA[3]);
                        accB[0] = ffma2(xB, wv0.x, accB[0]);
                        accB[1] = ffma2(xB, wv0.y, accB[1]);
                        accB[2] = ffma2(xB, wv1.x, accB[2]);
                        accB[3] = ffma2(xB, wv1.y, accB[3]);
                    }
                }
                __syncthreads();
            }
#pragma unroll
            for (int p = 0; p < 4; p++) {
                sEpi[lane * 33 + wb + 2 * p] = accA[p];
                sEpi[(lane + 32) * 33 + wb + 2 * p] = accB[p];
            }
            __syncthreads();
            u64* xw1u = (u64*)g_xw1v;
            for (int i = tid; i < 2048; i += BS) {      // raw store (prescale later)
                int r = i >> 5, s = i & 31;
                if (row0 + r < N)
                    xw1u[(size_t)(row0 + r) * 32 + s] = sEpi[r * 33 + s];
            }
            __syncthreads();
        }
    }
    gbar(ebase + 2);

    // ---------------- phase C: dinv + per-chunk(256) count scan -------------
    {
        const int r0 = b * 256 + tid;
        int c0 = 0;
        if (r0 < N) {
            u64 pc = g_degcnt[r0];
            c0 = (int)(pc >> 42);
            g_dinv[r0] = rsqrtf(1.0f + (float)(pc & ((1ull << 42) - 1)) * (1.0f / 16777216.0f));
        }
        s_scan[tid] = c0;
        __syncthreads();
        for (int off = 1; off < BS; off <<= 1) {
            int a = (tid >= off) ? s_scan[tid - off] : 0;
            __syncthreads();
            s_scan[tid] += a;
            __syncthreads();
        }
        if (r0 < N) g_rowptr[r0] = s_scan[tid] - c0;    // pre-offset
        if (tid == BS - 1) g_bsums[b] = s_scan[BS - 1];
    }
    gbar(ebase + 3);

    // ---------------- phase F: local block-prefix + fill + prescale ---------
    {
        // exclusive prefix of g_bsums[0..512) into persistent s_pfx
        int i0 = tid, i1 = tid + 256;
        int v0 = g_bsums[i0], v1 = g_bsums[i1];
        s_pfx[i0] = v0; s_pfx[i1] = v1;
        __syncthreads();
        for (int off = 1; off < 512; off <<= 1) {
            int a0 = (i0 >= off) ? s_pfx[i0 - off] : 0;
            int a1 = (i1 >= off) ? s_pfx[i1 - off] : 0;
            __syncthreads();
            s_pfx[i0] += a0; s_pfx[i1] += a1;
            __syncthreads();
        }
        s_pfx[i0] -= v0; s_pfx[i1] -= v1;               // exclusive
        __syncthreads();
    }
    for (int e = gtid; e < E; e += NT) {                // fill CSR, no atomics
        int s, d;
        if (is64) {
            const long long* p = (const long long*)ei;
            s = (int)p[e]; d = (int)p[(size_t)E + e];
        } else {
            const int* p = (const int*)ei;
            s = p[e]; d = p[(size_t)E + e];
        }
        int slot = g_rowptr[d] + s_pfx[d >> 8] + (int)g_slot[e];
        g_csr[slot] = ((u64)__float_as_uint(ew[e]) << 32) | (u32)s;
    }
    for (int i = gtid; i < N * 16; i += NT) {           // prescale xw1 by dinv
        int row = i >> 4;
        ulonglong2 v = g_xw1v[i];
        u64 dn2 = dup2(__float_as_uint(g_dinv[row]));
        v.x = ffma2(dn2, v.x, 0ull);
        v.y = ffma2(dn2, v.y, 0ull);
        g_xw1v[i] = v;
    }
    gbar(ebase + 4);

    // ---------------- phase G: SpMM1 (MLP=8) + f32x2 projection -------------
    for (int i = tid; i < HID * CLS; i += BS) {
        int k = i >> 5, c = i & 31;
        float v = W2[k * CLS + c];
        int c2 = (k & 31) >> 1;
        float* base = (float*)((k >= 32) ? s_w2b : s_w2a);
        base[(c2 * 32 + c) * 2 + (k & 1)] = v;
    }
    __syncthreads();
    const int slot = lane >> 4, cc = lane & 15;
    float b1a = b1[2 * cc], b1b = b1[2 * cc + 1];
    float b1c = b1[32 + 2 * cc], b1d = b1[33 + 2 * cc];
    u64* buf = s_ebuf[wid];
    const u32* bufw = (const u32*)buf;
    for (;;) {
        int chunk;
        if (lane == 0) chunk = atomicAdd(&g_tickets[1], 1) - s_tb1;
        chunk = __shfl_sync(0xffffffffu, chunk, 0);
        int row0c = chunk * 8;
        if (row0c >= N) break;
        int row1c = row0c + 8 < N ? row0c + 8 : N;
        for (int row = row0c; row < row1c; row++) {
            float dn = g_dinv[row];
            u64 acc01 = 0ull, acc23 = 0ull;
            if (slot == 0) {
                ulonglong2 sv = g_xw1v[(size_t)row * 16 + cc];
                acc01 = sv.x; acc23 = sv.y;             // prescaled self row
            }
            int p = g_rowptr[row] + s_pfx[row >> 8];
            int pe = (row + 1 < N) ? (g_rowptr[row + 1] + s_pfx[(row + 1) >> 8]) : E;
            while (p < pe) {
                int m = pe - p; if (m > 32) m = 32;
                buf[lane] = (lane < m) ? g_csr[p + lane] : 0ull;
                __syncwarp();
                int pairs = (m + 1) >> 1;
                int t = 0;
                for (; t + 8 <= pairs; t += 8) {
                    ulonglong2 v[8];
#pragma unroll
                    for (int i = 0; i < 8; i++) {
                        u32 src = bufw[(2 * (t + i) + slot) * 2];
                        v[i] = g_xw1v[(size_t)src * 16 + cc];
                    }
#pragma unroll
                    for (int i = 0; i < 8; i++) {
                        u64 w = dup2(bufw[(2 * (t + i) + slot) * 2 + 1]);
                        acc01 = ffma2(w, v[i].x, acc01);
                        acc23 = ffma2(w, v[i].y, acc23);
                    }
                }
                for (; t < pairs; t++) {
                    u32 src = bufw[(2 * t + slot) * 2];
                    u64 w = dup2(bufw[(2 * t + slot) * 2 + 1]);
                    ulonglong2 v0 = g_xw1v[(size_t)src * 16 + cc];
                    acc01 = ffma2(w, v0.x, acc01);
                    acc23 = ffma2(w, v0.y, acc23);
                }
                __syncwarp();
                p += 32;
            }
            float2 a01 = unpk(acc01), a23 = unpk(acc23);
            a01.x += __shfl_xor_sync(0xffffffffu, a01.x, 16);
            a01.y += __shfl_xor_sync(0xffffffffu, a01.y, 16);
            a23.x += __shfl_xor_sync(0xffffffffu, a23.x, 16);
            a23.y += __shfl_xor_sync(0xffffffffu, a23.y, 16);
            float hx = fmaxf(dn * a01.x + b1a, 0.0f);
            float hy = fmaxf(dn * a01.y + b1b, 0.0f);
            float hz = fmaxf(dn * a23.x + b1c, 0.0f);
            float hw = fmaxf(dn * a23.y + b1d, 0.0f);
            if (slot == 0)
                ((float4*)s_hrow[wid])[cc] = make_float4(hx, hy, hz, hw);
            __syncwarp();
            u64 accp = 0ull;
            const float4* hr = (const float4*)s_hrow[wid];
#pragma unroll
            for (int c2 = 0; c2 < 16; c2++) {
                float4 hv = hr[c2];
                accp = ffma2(pack2f(hv.x, hv.y), s_w2a[c2 * 32 + lane], accp);
                accp = ffma2(pack2f(hv.z, hv.w), s_w2b[c2 * 32 + lane], accp);
            }
            float2 ap = unpk(accp);
            ((float*)(g_xw2v + (size_t)row * 8))[lane] = dn * (ap.x + ap.y);
            __syncwarp();
        }
    }
    gbar(ebase + 5);

    // ---------------- phase H: SpMM2 (MLP=8) -> out -------------------------
    {
        float2 b2v = ((const float2*)b2)[cc];
        const u64* X2 = (const u64*)g_xw2v;
        for (;;) {
            int chunk;
            if (lane == 0) chunk = atomicAdd(&g_tickets[2], 1) - s_tb2;
            chunk = __shfl_sync(0xffffffffu, chunk, 0);
            int row0c = chunk * 8;
            if (row0c >= N) break;
            int row1c = row0c + 8 < N ? row0c + 8 : N;
            for (int row = row0c; row < row1c; row++) {
                float dn = g_dinv[row];
                u64 acc = 0ull;
                if (slot == 0) acc = X2[(size_t)row * 16 + cc];
                int p = g_rowptr[row] + s_pfx[row >> 8];
                int pe = (row + 1 < N) ? (g_rowptr[row + 1] + s_pfx[(row + 1) >> 8]) : E;
                while (p < pe) {
                    int m = pe - p; if (m > 32) m = 32;
                    buf[lane] = (lane < m) ? g_csr[p + lane] : 0ull;
                    __syncwarp();
                    int pairs = (m + 1) >> 1;
                    int t = 0;
                    for (; t + 8 <= pairs; t += 8) {
                        u64 v[8];
#pragma unroll
                        for (int i = 0; i < 8; i++) {
                            u32 src = bufw[(2 * (t + i) + slot) * 2];
                            v[i] = X2[(size_t)src * 16 + cc];
                        }
#pragma unroll
                        for (int i = 0; i < 8; i++) {
                            u64 w = dup2(bufw[(2 * (t + i) + slot) * 2 + 1]);
                            acc = ffma2(w, v[i], acc);
                        }
                    }
                    for (; t < pairs; t++) {
                        u32 src = bufw[(2 * t + slot) * 2];
                        u64 w = dup2(bufw[(2 * t + slot) * 2 + 1]);
                        acc = ffma2(w, X2[(size_t)src * 16 + cc], acc);
                    }
                    __syncwarp();
                    p += 32;
                }
                float2 a = unpk(acc);
                a.x += __shfl_xor_sync(0xffffffffu, a.x, 16);
                a.y += __shfl_xor_sync(0xffffffffu, a.y, 16);
                if (slot == 0)
                    ((float2*)(out + (size_t)row * CLS))[cc] =
                        make_float2(dn * a.x + b2v.x, dn * a.y + b2v.y);
            }
        }
    }

    // ---------------- tail: re-zero degcnt for the next replay --------------
    for (int i = gtid; i < N; i += NT) g_degcnt[i] = 0ull;
}

// ---------------------------------------------------------------------------
extern "C" void kernel_launch(void* const* d_in, const int* in_sizes, int n_in,
                              void* d_out, int out_size) {
    const float* x  = (const float*)d_in[0];
    const void*  ei = d_in[1];
    const float* ew = (const float*)d_in[2];
    const float* W1 = (const float*)d_in[3];
    const float* b1 = (const float*)d_in[4];
    const float* W2 = (const float*)d_in[5];
    const float* b2 = (const float*)d_in[6];
    float* out = (float*)d_out;

    int E = in_sizes[2];
    int N = in_sizes[0] / FIN1;
    if (N > N_MAXC) N = N_MAXC;
    if (E > E_MAXC) E = E_MAXC;

    mega<<<NB, BS>>>(x, ei, ew, W1, b1, W2, b2, out, N, E);
}

// round 13
// speedup vs baseline: 1.6889x; 1.0500x over previous
#include <cuda_runtime.h>
#include <cuda_fp16.h>
#include <stdint.h>

// ---------------------------------------------------------------------------
// 2-layer GCN, single persistent kernel. Round 11: fp16 xw1 (1 line/edge
// gather floor in SpMM1). Everything else identical to round 10.
// ---------------------------------------------------------------------------

#define N_MAXC  100000
#define E_MAXC  1700000
#define FIN1    128
#define HID     64
#define CLS     32
#define NB      512
#define BS      256
#define NT      (NB * BS)

typedef unsigned long long u64;
typedef unsigned int u32;

// ---- device scratch ----
__device__ u64        g_degcnt[N_MAXC];        // (count<<42)|fixed24(sum ew); 0 at entry
__device__ u32        g_slot[E_MAXC];
__device__ int        g_rowptr[N_MAXC + 1];    // intra-chunk exclusive counts
__device__ float      g_dinv[N_MAXC];
__device__ int        g_bsums[NB];
__device__ u64        g_csr[E_MAXC];           // (f32bits(ew)<<32)|src
__device__ u64        g_xw1h[(size_t)N_MAXC * 16];  // fp16 permuted xw1, 12.8MB
__device__ ulonglong2 g_xw2v[(size_t)N_MAXC * 8];   // fp32 xw2
__device__ int        g_tickets[4];            // monotonic across runs
__device__ int        g_count;
__device__ int        g_gen;

// ---- packed f32x2 helpers ----
__device__ __forceinline__ u64 ffma2(u64 a, u64 b, u64 c) {
    u64 d;
    asm("fma.rn.f32x2 %0, %1, %2, %3;" : "=l"(d) : "l"(a), "l"(b), "l"(c));
    return d;
}
__device__ __forceinline__ u64 dup2(u32 w) {
    u64 d;
    asm("mov.b64 %0, {%1, %1};" : "=l"(d) : "r"(w));
    return d;
}
__device__ __forceinline__ u64 pack2f(float x, float y) {
    u64 d;
    asm("mov.b64 %0, {%1, %2};" : "=l"(d) : "r"(__float_as_uint(x)), "r"(__float_as_uint(y)));
    return d;
}
__device__ __forceinline__ float2 unpk(u64 v) {
    float2 f;
    asm("mov.b64 {%0, %1}, %2;" : "=f"(f.x), "=f"(f.y) : "l"(v));
    return f;
}
__device__ __forceinline__ u32 f2h2(float lo, float hi) {
    u32 r;
    asm("cvt.rn.f16x2.f32 %0, %1, %2;" : "=r"(r) : "f"(hi), "f"(lo));
    return r;
}
__device__ __forceinline__ float2 h2f2(u32 v) {
    __half2 h = *(__half2*)&v;
    return __half22float2(h);
}

// ---- grid barrier ----
__device__ __forceinline__ void gbar(int expect) {
    __syncthreads();
    if (threadIdx.x == 0) {
        __threadfence();
        int t = atomicAdd(&g_count, 1);
        if (t == NB - 1) {
            g_count = 0;
            __threadfence();
            *(volatile int*)&g_gen = expect;
        } else {
            while (*(volatile int*)&g_gen - expect < 0) {}
            __threadfence();
        }
    }
    __syncthreads();
}

__global__ void __launch_bounds__(BS, 4) mega(
    const float* __restrict__ x, const void* __restrict__ ei,
    const float* __restrict__ ew, const float* __restrict__ W1,
    const float* __restrict__ b1, const float* __restrict__ W2,
    const float* __restrict__ b2, float* __restrict__ out,
    int N, int E)
{
    __shared__ __align__(16) char s_mem[33792 + 4096];
    __shared__ int s_is64, s_tile, s_tb0, s_tb1, s_tb2;

    float* sX   = (float*)s_mem;                  // GEMM: [64][132]
    float* sW   = (float*)(s_mem + 33792);        // GEMM: [16][64]
    u32*   sEpiH = (u32*)s_mem;                   // GEMM epi: [64][33] u32 (half2)
    int*   s_scan = (int*)s_mem;                  // C scan
    u64*   s_w2a = (u64*)s_mem;                   // proj pairs lo
    u64*   s_w2b = (u64*)(s_mem + 4096);          // proj pairs hi
    u64 (*s_ebuf)[32] = (u64(*)[32])(s_mem + 8192);
    float (*s_hrow)[HID] = (float(*)[HID])(s_mem + 8192 + 2048);
    int*   s_pfx = (int*)(s_mem + 16384);         // block prefix, persists F..H

    const int tid = threadIdx.x;
    const int b   = blockIdx.x;
    const int gtid = b * BS + tid;
    const int wid = tid >> 5, lane = tid & 31;

    // ---------------- entry: bases + i32/i64 detect -------------------------
    int ebase = 0;
    if (tid == 0) {
        ebase = *(volatile int*)&g_gen;
        s_tb0 = *(volatile int*)&g_tickets[0];
        s_tb1 = *(volatile int*)&g_tickets[1];
        s_tb2 = *(volatile int*)&g_tickets[2];
    }
    if (tid < 32) {
        const u32* u = (const u32*)ei;
        int cnt = E < 64 ? E : 64;
        bool nz = false;
        for (int j = tid; j < cnt; j += 32) nz |= (u[2 * j + 1] != 0u);
        u32 bl = __ballot_sync(0xffffffffu, nz);
        if (tid == 0) s_is64 = (bl == 0u) ? 1 : 0;
    }
    gbar(ebase + 1);
    const int is64 = s_is64;

    // ---------------- phase B: edge atomics+slots overlapped with GEMM ------
    for (int e = gtid; e < E; e += NT) {
        int d = is64 ? (int)((const long long*)ei)[(size_t)E + e]
                     : ((const int*)ei)[(size_t)E + e];
        u64 add = (1ull << 42) | (u64)(u32)__float2uint_rn(ew[e] * 16777216.0f);
        u64 old = atomicAdd(&g_degcnt[d], add);
        g_slot[e] = (u32)(old >> 42);
    }
    {
        const int ntiles = (N + 63) / 64;
        const int w8 = wid * 8;
        for (;;) {
            if (tid == 0) s_tile = atomicAdd(&g_tickets[0], 1) - s_tb0;
            __syncthreads();
            const int tile = s_tile;
            if (tile >= ntiles) break;
            const int row0 = tile * 64;
            for (int i = tid; i < 2048; i += BS) {
                int r = i >> 5, k4 = i & 31;
                float4 v = make_float4(0.f, 0.f, 0.f, 0.f);
                if (row0 + r < N)
                    v = ((const float4*)(x + (size_t)(row0 + r) * FIN1))[k4];
                *(float4*)&sX[r * 132 + 4 * k4] = v;
            }
            __syncthreads();

            u64 accA[4], accB[4];
#pragma unroll
            for (int j = 0; j < 4; j++) { accA[j] = 0ull; accB[j] = 0ull; }

            for (int c = 0; c < 8; c++) {
                {
                    int k = tid >> 4, c4 = tid & 15;
                    *(float4*)&sW[k * 64 + 4 * c4] =
                        ((const float4*)(W1 + (size_t)(c * 16 + k) * HID))[c4];
                }
                __syncthreads();
                const float4* xpA = (const float4*)&sX[lane * 132 + c * 16];
                const float4* xpB = (const float4*)&sX[(lane + 32) * 132 + c * 16];
#pragma unroll
                for (int k4 = 0; k4 < 4; k4++) {
                    float4 xa = xpA[k4];
                    float4 xb = xpB[k4];
                    float xsA[4] = {xa.x, xa.y, xa.z, xa.w};
                    float xsB[4] = {xb.x, xb.y, xb.z, xb.w};
#pragma unroll
                    for (int kk = 0; kk < 4; kk++) {
                        int k = k4 * 4 + kk;
                        ulonglong2 wv0 = *(const ulonglong2*)&sW[k * 64 + w8];
                        ulonglong2 wv1 = *(const ulonglong2*)&sW[k * 64 + w8 + 4];
                        u64 xA = dup2(__float_as_uint(xsA[kk]));
                        u64 xB = dup2(__float_as_uint(xsB[kk]));
                        accA[0] = ffma2(xA, wv0.x, accA[0]);
                        accA[1] = ffma2(xA, wv0.y, accA[1]);
                        accA[2] = ffma2(xA, wv1.x, accA[2]);
                        accA[3] = ffma2(xA, wv1.y, accA[3]);
                        accB[0] = ffma2(xB, wv0.x, accB[0]);
                        accB[1] = ffma2(xB, wv0.y, accB[1]);
                        accB[2] = ffma2(xB, wv1.x, accB[2]);
                        accB[3] = ffma2(xB, wv1.y, accB[3]);
                    }
                }
                __syncthreads();
            }
            // epilogue: f32x2 -> half2, transpose via smem, coalesced store.
            // logical col (2cc,2cc+1) -> u32 2cc (lo of u64 slot cc);
            // cols (32+2cc,33+2cc)    -> u32 2cc+1 (hi of slot cc).
            {
                int cbase = (wid & 3) * 4;          // cc base for this warp
                int hilo = (wid >> 2);              // 0: lo half, 1: hi half
#pragma unroll
                for (int j = 0; j < 4; j++) {
                    float2 fa = unpk(accA[j]);
                    float2 fb = unpk(accB[j]);
                    int idx = 2 * (cbase + j) + hilo;
                    sEpiH[lane * 33 + idx] = f2h2(fa.x, fa.y);
                    sEpiH[(lane + 32) * 33 + idx] = f2h2(fb.x, fb.y);
                }
            }
            __syncthreads();
            u32* xw1u = (u32*)g_xw1h;
            for (int i = tid; i < 2048; i += BS) {
                int r = i >> 5, s = i & 31;
                if (row0 + r < N)
                    xw1u[(size_t)(row0 + r) * 32 + s] = sEpiH[r * 33 + s];
            }
            __syncthreads();
        }
    }
    gbar(ebase + 2);

    // ---------------- phase C: dinv + per-chunk(256) count scan -------------
    {
        const int r0 = b * 256 + tid;
        int c0 = 0;
        if (r0 < N) {
            u64 pc = g_degcnt[r0];
            c0 = (int)(pc >> 42);
            g_dinv[r0] = rsqrtf(1.0f + (float)(pc & ((1ull << 42) - 1)) * (1.0f / 16777216.0f));
        }
        s_scan[tid] = c0;
        __syncthreads();
        for (int off = 1; off < BS; off <<= 1) {
            int a = (tid >= off) ? s_scan[tid - off] : 0;
            __syncthreads();
            s_scan[tid] += a;
            __syncthreads();
        }
        if (r0 < N) g_rowptr[r0] = s_scan[tid] - c0;
        if (tid == BS - 1) g_bsums[b] = s_scan[BS - 1];
    }
    gbar(ebase + 3);

    // ---------------- phase F: block-prefix + fill + fp16 prescale ----------
    {
        int i0 = tid, i1 = tid + 256;
        int v0 = g_bsums[i0], v1 = g_bsums[i1];
        s_pfx[i0] = v0; s_pfx[i1] = v1;
        __syncthreads();
        for (int off = 1; off < 512; off <<= 1) {
            int a0 = (i0 >= off) ? s_pfx[i0 - off] : 0;
            int a1 = (i1 >= off) ? s_pfx[i1 - off] : 0;
            __syncthreads();
            s_pfx[i0] += a0; s_pfx[i1] += a1;
            __syncthreads();
        }
        s_pfx[i0] -= v0; s_pfx[i1] -= v1;
        __syncthreads();
    }
    for (int e = gtid; e < E; e += NT) {
        int s, d;
        if (is64) {
            const long long* p = (const long long*)ei;
            s = (int)p[e]; d = (int)p[(size_t)E + e];
        } else {
            const int* p = (const int*)ei;
            s = p[e]; d = p[(size_t)E + e];
        }
        int slot = g_rowptr[d] + s_pfx[d >> 8] + (int)g_slot[e];
        g_csr[slot] = ((u64)__float_as_uint(ew[e]) << 32) | (u32)s;
    }
    {
        u32* xw1u = (u32*)g_xw1h;
        for (int i = gtid; i < N * 32; i += NT) {     // prescale xw1 by dinv
            int row = i >> 5;
            float dn = g_dinv[row];
            float2 f = h2f2(xw1u[i]);
            xw1u[i] = f2h2(dn * f.x, dn * f.y);
        }
    }
    gbar(ebase + 4);

    // ---------------- phase G: SpMM1 (fp16 gather, 1 line/edge) + proj ------
    for (int i = tid; i < HID * CLS; i += BS) {
        int k = i >> 5, c = i & 31;
        float v = W2[k * CLS + c];
        int c2 = (k & 31) >> 1;
        float* base = (float*)((k >= 32) ? s_w2b : s_w2a);
        base[(c2 * 32 + c) * 2 + (k & 1)] = v;
    }
    __syncthreads();
    const int slot = lane >> 4, cc = lane & 15;
    float b1a = b1[2 * cc], b1b = b1[2 * cc + 1];
    float b1c = b1[32 + 2 * cc], b1d = b1[33 + 2 * cc];
    u64* buf = s_ebuf[wid];
    const u32* bufw = (const u32*)buf;
    for (;;) {
        int chunk;
        if (lane == 0) chunk = atomicAdd(&g_tickets[1], 1) - s_tb1;
        chunk = __shfl_sync(0xffffffffu, chunk, 0);
        int row0c = chunk * 8;
        if (row0c >= N) break;
        int row1c = row0c + 8 < N ? row0c + 8 : N;
        for (int row = row0c; row < row1c; row++) {
            float dn = g_dinv[row];
            float a0 = 0.f, a1 = 0.f, a2 = 0.f, a3 = 0.f;
            if (slot == 0) {
                u64 sv = g_xw1h[(size_t)row * 16 + cc];    // prescaled self
                float2 flo = h2f2((u32)sv);
                float2 fhi = h2f2((u32)(sv >> 32));
                a0 = flo.x; a1 = flo.y; a2 = fhi.x; a3 = fhi.y;
            }
            int p = g_rowptr[row] + s_pfx[row >> 8];
            int pe = (row + 1 < N) ? (g_rowptr[row + 1] + s_pfx[(row + 1) >> 8]) : E;
            while (p < pe) {
                int m = pe - p; if (m > 32) m = 32;
                buf[lane] = (lane < m) ? g_csr[p + lane] : 0ull;
                __syncwarp();
                int pairs = (m + 1) >> 1;
                int t = 0;
                for (; t + 8 <= pairs; t += 8) {
                    u64 v[8];
#pragma unroll
                    for (int i = 0; i < 8; i++) {
                        u32 src = bufw[(2 * (t + i) + slot) * 2];
                        v[i] = g_xw1h[(size_t)src * 16 + cc];
                    }
#pragma unroll
                    for (int i = 0; i < 8; i++) {
                        float w = __uint_as_float(bufw[(2 * (t + i) + slot) * 2 + 1]);
                        float2 flo = h2f2((u32)v[i]);
                        float2 fhi = h2f2((u32)(v[i] >> 32));
                        a0 = fmaf(w, flo.x, a0); a1 = fmaf(w, flo.y, a1);
                        a2 = fmaf(w, fhi.x, a2); a3 = fmaf(w, fhi.y, a3);
                    }
                }
                for (; t < pairs; t++) {
                    u32 src = bufw[(2 * t + slot) * 2];
                    float w = __uint_as_float(bufw[(2 * t + slot) * 2 + 1]);
                    u64 v0 = g_xw1h[(size_t)src * 16 + cc];
                    float2 flo = h2f2((u32)v0);
                    float2 fhi = h2f2((u32)(v0 >> 32));
                    a0 = fmaf(w, flo.x, a0); a1 = fmaf(w, flo.y, a1);
                    a2 = fmaf(w, fhi.x, a2); a3 = fmaf(w, fhi.y, a3);
                }
                __syncwarp();
                p += 32;
            }
            a0 += __shfl_xor_sync(0xffffffffu, a0, 16);
            a1 += __shfl_xor_sync(0xffffffffu, a1, 16);
            a2 += __shfl_xor_sync(0xffffffffu, a2, 16);
            a3 += __shfl_xor_sync(0xffffffffu, a3, 16);
            float hx = fmaxf(dn * a0 + b1a, 0.0f);
            float hy = fmaxf(dn * a1 + b1b, 0.0f);
            float hz = fmaxf(dn * a2 + b1c, 0.0f);
            float hw = fmaxf(dn * a3 + b1d, 0.0f);
            if (slot == 0)
                ((float4*)s_hrow[wid])[cc] = make_float4(hx, hy, hz, hw);
            __syncwarp();
            u64 accp = 0ull;
            const float4* hr = (const float4*)s_hrow[wid];
#pragma unroll
            for (int c2 = 0; c2 < 16; c2++) {
                float4 hv = hr[c2];
                accp = ffma2(pack2f(hv.x, hv.y), s_w2a[c2 * 32 + lane], accp);
                accp = ffma2(pack2f(hv.z, hv.w), s_w2b[c2 * 32 + lane], accp);
            }
            float2 ap = unpk(accp);
            ((float*)(g_xw2v + (size_t)row * 8))[lane] = dn * (ap.x + ap.y);
            __syncwarp();
        }
    }
    gbar(ebase + 5);

    // ---------------- phase H: SpMM2 (fp32, MLP=8) -> out -------------------
    {
        float2 b2v = ((const float2*)b2)[cc];
        const u64* X2 = (const u64*)g_xw2v;
        for (;;) {
            int chunk;
            if (lane == 0) chunk = atomicAdd(&g_tickets[2], 1) - s_tb2;
            chunk = __shfl_sync(0xffffffffu, chunk, 0);
            int row0c = chunk * 8;
            if (row0c >= N) break;
            int row1c = row0c + 8 < N ? row0c + 8 : N;
            for (int row = row0c; row < row1c; row++) {
                float dn = g_dinv[row];
                u64 acc = 0ull;
                if (slot == 0) acc = X2[(size_t)row * 16 + cc];
                int p = g_rowptr[row] + s_pfx[row >> 8];
                int pe = (row + 1 < N) ? (g_rowptr[row + 1] + s_pfx[(row + 1) >> 8]) : E;
                while (p < pe) {
                    int m = pe - p; if (m > 32) m = 32;
                    buf[lane] = (lane < m) ? g_csr[p + lane] : 0ull;
                    __syncwarp();
                    int pairs = (m + 1) >> 1;
                    int t = 0;
                    for (; t + 8 <= pairs; t += 8) {
                        u64 v[8];
#pragma unroll
                        for (int i = 0; i < 8; i++) {
                            u32 src = bufw[(2 * (t + i) + slot) * 2];
                            v[i] = X2[(size_t)src * 16 + cc];
                        }
#pragma unroll
                        for (int i = 0; i < 8; i++) {
                            u64 w = dup2(bufw[(2 * (t + i) + slot) * 2 + 1]);
                            acc = ffma2(w, v[i], acc);
                        }
                    }
                    for (; t < pairs; t++) {
                        u32 src = bufw[(2 * t + slot) * 2];
                        u64 w = dup2(bufw[(2 * t + slot) * 2 + 1]);
                        acc = ffma2(w, X2[(size_t)src * 16 + cc], acc);
                    }
                    __syncwarp();
                    p += 32;
                }
                float2 a = unpk(acc);
                a.x += __shfl_xor_sync(0xffffffffu, a.x, 16);
                a.y += __shfl_xor_sync(0xffffffffu, a.y, 16);
                if (slot == 0)
                    ((float2*)(out + (size_t)row * CLS))[cc] =
                        make_float2(dn * a.x + b2v.x, dn * a.y + b2v.y);
            }
        }
    }

    // ---------------- tail: re-zero degcnt for the next replay --------------
    for (int i = gtid; i < N; i += NT) g_degcnt[i] = 0ull;
}

// ---------------------------------------------------------------------------
extern "C" void kernel_launch(void* const* d_in, const int* in_sizes, int n_in,
                              void* d_out, int out_size) {
    const float* x  = (const float*)d_in[0];
    const void*  ei = d_in[1];
    const float* ew = (const float*)d_in[2];
    const float* W1 = (const float*)d_in[3];
    const float* b1 = (const float*)d_in[4];
    const float* W2 = (const float*)d_in[5];
    const float* b2 = (const float*)d_in[6];
    float* out = (float*)d_out;

    int E = in_sizes[2];
    int N = in_sizes[0] / FIN1;
    if (N > N_MAXC) N = N_MAXC;
    if (E > E_MAXC) E = E_MAXC;

    mega<<<NB, BS>>>(x, ei, ew, W1, b1, W2, b2, out, N, E);
}